// round 6
// baseline (speedup 1.0000x reference)
#include <cuda_runtime.h>
#include <math.h>

#define BB 4
#define SS 2048
#define EE 512
#define HH 8
#define HD 64
#define SCALE 0.04419417382415922f  /* 512^-0.5 (reference scales by E, not HD) */

// Scratch (static device arrays — allocation rules forbid cudaMalloc)
__device__ float g_q[BB * HH * SS * HD];
__device__ float g_k[BB * HH * SS * HD];
__device__ float g_v[BB * HH * SS * HD];

// ---------------------------------------------------------------------------
// helpers
// ---------------------------------------------------------------------------
// pack {upper=hi, lower=lo} bf16x2
__device__ __forceinline__ unsigned pk2(float hi, float lo) {
    unsigned r; asm("cvt.rn.bf16x2.f32 %0, %1, %2;" : "=r"(r) : "f"(hi), "f"(lo)); return r;
}
// pack {upper=hi, lower=lo} f16x2
__device__ __forceinline__ unsigned pkh(float hi, float lo) {
    unsigned r; asm("cvt.rn.f16x2.f32 %0, %1, %2;" : "=r"(r) : "f"(hi), "f"(lo)); return r;
}
__device__ __forceinline__ float lo16f(unsigned u) { return __uint_as_float(u << 16); }
__device__ __forceinline__ float hi16f(unsigned u) { return __uint_as_float(u & 0xffff0000u); }

// bf16 m16n8k16
__device__ __forceinline__ void mma16(float4& c,
    unsigned a0, unsigned a1, unsigned a2, unsigned a3, unsigned b0, unsigned b1)
{
    asm("mma.sync.aligned.m16n8k16.row.col.f32.bf16.bf16.f32 "
        "{%0,%1,%2,%3}, {%4,%5,%6,%7}, {%8,%9}, {%0,%1,%2,%3};"
        : "+f"(c.x), "+f"(c.y), "+f"(c.z), "+f"(c.w)
        : "r"(a0), "r"(a1), "r"(a2), "r"(a3), "r"(b0), "r"(b1));
}
// fp16 m16n8k16
__device__ __forceinline__ void mmah(float4& c,
    unsigned a0, unsigned a1, unsigned a2, unsigned a3, unsigned b0, unsigned b1)
{
    asm("mma.sync.aligned.m16n8k16.row.col.f32.f16.f16.f32 "
        "{%0,%1,%2,%3}, {%4,%5,%6,%7}, {%8,%9}, {%0,%1,%2,%3};"
        : "+f"(c.x), "+f"(c.y), "+f"(c.z), "+f"(c.w)
        : "r"(a0), "r"(a1), "r"(a2), "r"(a3), "r"(b0), "r"(b1));
}
__device__ __forceinline__ void cpa16(float* dst, const float* src) {
    unsigned sa = (unsigned)__cvta_generic_to_shared(dst);
    asm volatile("cp.async.cg.shared.global [%0], [%1], 16;" :: "r"(sa), "l"(src));
}
#define CP_COMMIT() asm volatile("cp.async.commit_group;")
#define CP_WAIT(n)  asm volatile("cp.async.wait_group %0;" :: "n"(n))

// ---------------------------------------------------------------------------
// Kernel 1: QKV projection.
//   z=0/1 (Q/K): fp16 single-pass m16n8k16 (2 k-steps/panel, was 4 tf32-k8).
//   z=2 (V): bf16 3-pass split (errors hit output linearly; keep exact).
// CTA 128x128, 8 warps, warp 64x32, K=32 panels double-buffered cp.async.
// ---------------------------------------------------------------------------
#define QKV_SMEM_BYTES (18432 * 4)

__global__ void __launch_bounds__(256, 1) qkv_mma_kernel(
    const float* __restrict__ x, const float* __restrict__ Wq,
    const float* __restrict__ Wk, const float* __restrict__ Wv)
{
    extern __shared__ float sm[];
    const int z = blockIdx.z;
    const float* W = z == 0 ? Wq : (z == 1 ? Wk : Wv);
    float* outp = z == 0 ? g_q : (z == 1 ? g_k : g_v);
    const int m0 = blockIdx.y * 128, n0 = blockIdx.x * 128;
    const int tid = threadIdx.x, lane = tid & 31, warp = tid >> 5;
    const int g = lane >> 2, t = lane & 3;
    const int mw = (warp >> 2) * 64, nw = (warp & 3) * 32;

    float* Xs[2] = { sm, sm + 4608 };
    float* Ws[2] = { sm + 9216, sm + 13824 };
    const int r_ = tid >> 1, c_ = (tid & 1) * 16;
    #define STAGE(buf, k0) do { \
        cpa16(Xs[buf] + r_ * 36 + c_,      &x[(size_t)(m0 + r_) * EE + (k0) + c_]); \
        cpa16(Xs[buf] + r_ * 36 + c_ + 4,  &x[(size_t)(m0 + r_) * EE + (k0) + c_ + 4]); \
        cpa16(Xs[buf] + r_ * 36 + c_ + 8,  &x[(size_t)(m0 + r_) * EE + (k0) + c_ + 8]); \
        cpa16(Xs[buf] + r_ * 36 + c_ + 12, &x[(size_t)(m0 + r_) * EE + (k0) + c_ + 12]); \
        cpa16(Ws[buf] + r_ * 36 + c_,      &W[(size_t)(n0 + r_) * EE + (k0) + c_]); \
        cpa16(Ws[buf] + r_ * 36 + c_ + 4,  &W[(size_t)(n0 + r_) * EE + (k0) + c_ + 4]); \
        cpa16(Ws[buf] + r_ * 36 + c_ + 8,  &W[(size_t)(n0 + r_) * EE + (k0) + c_ + 8]); \
        cpa16(Ws[buf] + r_ * 36 + c_ + 12, &W[(size_t)(n0 + r_) * EE + (k0) + c_ + 12]); \
        CP_COMMIT(); \
    } while (0)

    float4 acc[4][4];
    #pragma unroll
    for (int m = 0; m < 4; m++)
        #pragma unroll
        for (int n = 0; n < 4; n++) acc[m][n] = make_float4(0.f, 0.f, 0.f, 0.f);

    STAGE(0, 0);
    for (int p = 0; p < 16; p++) {
        if (p < 15) STAGE((p + 1) & 1, (p + 1) * 32);
        if (p < 15) { CP_WAIT(1); } else { CP_WAIT(0); }
        __syncthreads();
        const float* Xb = Xs[p & 1];
        const float* Wb = Ws[p & 1];

        if (z < 2) {
            // ---- fp16 single-pass: 2 k16 steps ----
            #pragma unroll
            for (int s = 0; s < 2; s++) {
                unsigned a[4][4], b[4][2];
                #pragma unroll
                for (int m = 0; m < 4; m++) {
                    const float* r0 = &Xb[(mw + 16 * m + g) * 36 + 16 * s];
                    const float* r1 = &Xb[(mw + 16 * m + g + 8) * 36 + 16 * s];
                    float2 f0 = *(const float2*)&r0[2 * t];
                    float2 f1 = *(const float2*)&r1[2 * t];
                    float2 f2 = *(const float2*)&r0[2 * t + 8];
                    float2 f3 = *(const float2*)&r1[2 * t + 8];
                    a[m][0] = pkh(f0.y, f0.x);
                    a[m][1] = pkh(f1.y, f1.x);
                    a[m][2] = pkh(f2.y, f2.x);
                    a[m][3] = pkh(f3.y, f3.x);
                }
                #pragma unroll
                for (int n = 0; n < 4; n++) {
                    const float* w0 = &Wb[(nw + 8 * n + g) * 36 + 16 * s];
                    float2 f0 = *(const float2*)&w0[2 * t];
                    float2 f1 = *(const float2*)&w0[2 * t + 8];
                    b[n][0] = pkh(f0.y, f0.x);
                    b[n][1] = pkh(f1.y, f1.x);
                }
                #pragma unroll
                for (int m = 0; m < 4; m++)
                    #pragma unroll
                    for (int n = 0; n < 4; n++)
                        mmah(acc[m][n], a[m][0], a[m][1], a[m][2], a[m][3], b[n][0], b[n][1]);
            }
        } else {
            // ---- bf16 3-pass split: 2 k16 steps ----
            #pragma unroll
            for (int s = 0; s < 2; s++) {
                unsigned ah[4][4], al[4][4], bh[4][2], bl[4][2];
                #pragma unroll
                for (int m = 0; m < 4; m++) {
                    const float* r0 = &Xb[(mw + 16 * m + g) * 36 + 16 * s];
                    const float* r1 = &Xb[(mw + 16 * m + g + 8) * 36 + 16 * s];
                    float2 f0 = *(const float2*)&r0[2 * t];
                    float2 f1 = *(const float2*)&r1[2 * t];
                    float2 f2 = *(const float2*)&r0[2 * t + 8];
                    float2 f3 = *(const float2*)&r1[2 * t + 8];
                    ah[m][0] = pk2(f0.y, f0.x); al[m][0] = pk2(f0.y - hi16f(ah[m][0]), f0.x - lo16f(ah[m][0]));
                    ah[m][1] = pk2(f1.y, f1.x); al[m][1] = pk2(f1.y - hi16f(ah[m][1]), f1.x - lo16f(ah[m][1]));
                    ah[m][2] = pk2(f2.y, f2.x); al[m][2] = pk2(f2.y - hi16f(ah[m][2]), f2.x - lo16f(ah[m][2]));
                    ah[m][3] = pk2(f3.y, f3.x); al[m][3] = pk2(f3.y - hi16f(ah[m][3]), f3.x - lo16f(ah[m][3]));
                }
                #pragma unroll
                for (int n = 0; n < 4; n++) {
                    const float* w0 = &Wb[(nw + 8 * n + g) * 36 + 16 * s];
                    float2 f0 = *(const float2*)&w0[2 * t];
                    float2 f1 = *(const float2*)&w0[2 * t + 8];
                    bh[n][0] = pk2(f0.y, f0.x); bl[n][0] = pk2(f0.y - hi16f(bh[n][0]), f0.x - lo16f(bh[n][0]));
                    bh[n][1] = pk2(f1.y, f1.x); bl[n][1] = pk2(f1.y - hi16f(bh[n][1]), f1.x - lo16f(bh[n][1]));
                }
                #pragma unroll
                for (int m = 0; m < 4; m++)
                    #pragma unroll
                    for (int n = 0; n < 4; n++) {
                        mma16(acc[m][n], ah[m][0], ah[m][1], ah[m][2], ah[m][3], bh[n][0], bh[n][1]);
                        mma16(acc[m][n], ah[m][0], ah[m][1], ah[m][2], ah[m][3], bl[n][0], bl[n][1]);
                        mma16(acc[m][n], al[m][0], al[m][1], al[m][2], al[m][3], bh[n][0], bh[n][1]);
                    }
            }
        }
        __syncthreads();
    }

    #pragma unroll
    for (int m = 0; m < 4; m++) {
        int r0 = m0 + mw + 16 * m + g, r1 = r0 + 8;
        int b0_ = r0 >> 11, s0_ = r0 & 2047;
        int b1_ = r1 >> 11, s1_ = r1 & 2047;
        #pragma unroll
        for (int n = 0; n < 4; n++) {
            int col = n0 + nw + 8 * n + 2 * t;
            int h = col >> 6, d = col & 63;
            *(float2*)&outp[(((size_t)b0_ * HH + h) * SS + s0_) * HD + d] = make_float2(acc[m][n].x, acc[m][n].y);
            *(float2*)&outp[(((size_t)b1_ * HH + h) * SS + s1_) * HD + d] = make_float2(acc[m][n].z, acc[m][n].w);
        }
    }
}

// ---------------------------------------------------------------------------
// Kernel 2: flash attention with relative-position skew.
//
// Srel[i,j] = q_i . Er[S-1-(i-j)]  (j<=i) | 0 (j=i+1) | q_{i+1} . Er[j-i-2] (j>=i+2)
//
// S, R1, R2: fp16 m16n8k16 single-pass (half the k8 instruction count).
// PV: bf16 m16n8k16 3-pass split (A-frags straight from softmax accumulators).
// ---------------------------------------------------------------------------
#define QP 68
#define KP2 72     /* packed half2 K^T rows: [32][72] */
#define VP 72
#define WP2 200    /* packed half2 Er windows: [32][200] */
#define RP 84
#define SM_Q  0
#define SM_K  (129 * QP)              /* 8772  */
#define SM_V  (SM_K + 32 * KP2)       /* 11076 */
#define SM_W1 (SM_V + 64 * VP)        /* 15684 */
#define SM_W2 (SM_W1 + 32 * WP2)      /* 22084 */
#define SM_R  (SM_W2 + 32 * WP2)      /* 28484 */
#define SM_TOT_FLOATS (SM_R + 128 * RP)   /* 39236 */
#define SMEM_BYTES (SM_TOT_FLOATS * 4)

__global__ void __launch_bounds__(256, 1) attn_kernel(
    const float* __restrict__ Er, float* __restrict__ out)
{
    extern __shared__ float sm[];
    float* Qs   = sm + SM_Q;              // [129][QP] fp32 Q rows (prologue only)
    unsigned* Khs = (unsigned*)(sm + SM_K);  // [32][KP2] half2 K^T [d2][j]
    float* Vs   = sm + SM_V;              // [64][VP]  fp32 V [j][d]
    unsigned* W1h = (unsigned*)(sm + SM_W1); // [32][WP2] half2 Er window 1
    unsigned* W2h = (unsigned*)(sm + SM_W2); // [32][WP2] half2 Er window 2
    float* Rscr = sm + SM_R;              // [128][RP] per-warp R scratch
    unsigned* Vth = (unsigned*)sm;           // [64][36] bf16x2 hi (overlays Qs)
    unsigned* Vtl = ((unsigned*)sm) + 2304;  // [64][36] bf16x2 lo

    const int tid  = threadIdx.x;
    const int lane = tid & 31;
    const int warp = tid >> 5;
    const int g = lane >> 2;     // 0..7
    const int t = lane & 3;      // 0..3
    const int rbase = warp * 16;

    const int bh = blockIdx.y;
    const int i0 = blockIdx.x * 128;

    const float* qb0 = g_q + (size_t)bh * SS * HD;
    const float* kb0 = g_k + (size_t)bh * SS * HD;
    const float* vb0 = g_v + (size_t)bh * SS * HD;

    // ---- stage Q rows i0..i0+128 ----
    for (int idx = tid; idx < 129 * 16; idx += 256) {
        int r = idx >> 4, dq = (idx & 15) * 4;
        float4 v = make_float4(0.f, 0.f, 0.f, 0.f);
        int gi = i0 + r;
        if (gi < SS) v = *(const float4*)&qb0[(size_t)gi * HD + dq];
        *(float4*)&Qs[r * QP + dq] = v;
    }
    __syncthreads();

    // ---- resident A fragments (fp16, 4 k16 steps) ----
    unsigned aq[4][4], aq2[4][4];
    {
        const float* r0 = &Qs[(rbase + g) * QP];
        const float* r1 = &Qs[(rbase + g + 8) * QP];
        const float* s0 = &Qs[(rbase + g + 1) * QP];
        const float* s1 = &Qs[(rbase + g + 9) * QP];
        #pragma unroll
        for (int s = 0; s < 4; s++) {
            float2 f0 = *(const float2*)&r0[16 * s + 2 * t];
            float2 f1 = *(const float2*)&r1[16 * s + 2 * t];
            float2 f2 = *(const float2*)&r0[16 * s + 2 * t + 8];
            float2 f3 = *(const float2*)&r1[16 * s + 2 * t + 8];
            aq[s][0] = pkh(f0.y, f0.x);
            aq[s][1] = pkh(f1.y, f1.x);
            aq[s][2] = pkh(f2.y, f2.x);
            aq[s][3] = pkh(f3.y, f3.x);
            float2 h0 = *(const float2*)&s0[16 * s + 2 * t];
            float2 h1 = *(const float2*)&s1[16 * s + 2 * t];
            float2 h2 = *(const float2*)&s0[16 * s + 2 * t + 8];
            float2 h3 = *(const float2*)&s1[16 * s + 2 * t + 8];
            aq2[s][0] = pkh(h0.y, h0.x);
            aq2[s][1] = pkh(h1.y, h1.x);
            aq2[s][2] = pkh(h2.y, h2.x);
            aq2[s][3] = pkh(h3.y, h3.x);
        }
    }
    __syncthreads();  // frag build done before Vth overwrites Qs

    float4 Oacc[8];
    #pragma unroll
    for (int n = 0; n < 8; n++) Oacc[n] = make_float4(0.f, 0.f, 0.f, 0.f);
    float m0r = -1e30f, m1r = -1e30f, l0r = 0.f, l1r = 0.f;

    const float* rp0 = &Rscr[(rbase + g) * RP];
    const float* rp1 = &Rscr[(rbase + g + 8) * RP];
    float* wr0 = &Rscr[(rbase + g) * RP + 2 * t];
    float* wr1 = &Rscr[(rbase + g + 8) * RP + 2 * t];
    const int off1w = 112 - rbase;
    const int tlb = 2 * t + 15 - g;
    const int diffb = (2 * t) - (i0 + rbase + g);

    for (int j0 = 0; j0 < SS; j0 += 64) {
        __syncthreads();  // previous tile compute done before restage

        const bool need1 = (j0 <= i0 + 127);
        const bool need2 = (j0 + 63 >= i0 + 2);
        const int L1 = SS - 128 - i0 + j0;
        const int L2 = j0 - i0 - 129;

        // ---- stage K^T packed half2 [d2][j], V fp32 ----
        for (int idx = tid; idx < 64 * 16; idx += 256) {
            int j = idx >> 4, dq = (idx & 15) * 4;
            float4 kv = *(const float4*)&kb0[(size_t)(j0 + j) * HD + dq];
            int d2 = dq >> 1;
            Khs[d2 * KP2 + j]       = pkh(kv.y, kv.x);
            Khs[(d2 + 1) * KP2 + j] = pkh(kv.w, kv.z);
            *(float4*)&Vs[j * VP + dq] = *(const float4*)&vb0[(size_t)(j0 + j) * HD + dq];
        }
        if (need1) {
            for (int idx = tid; idx < 192 * 16; idx += 256) {
                int tl = idx >> 4, dq = (idx & 15) * 4;
                int l = L1 + tl;
                float4 e = make_float4(0.f, 0.f, 0.f, 0.f);
                if (l >= 0 && l < SS) e = *(const float4*)&Er[(size_t)l * HD + dq];
                int d2 = dq >> 1;
                W1h[d2 * WP2 + tl]       = pkh(e.y, e.x);
                W1h[(d2 + 1) * WP2 + tl] = pkh(e.w, e.z);
            }
        }
        if (need2) {
            for (int idx = tid; idx < 192 * 16; idx += 256) {
                int tl = idx >> 4, dq = (idx & 15) * 4;
                int l = L2 + tl;
                float4 e = make_float4(0.f, 0.f, 0.f, 0.f);
                if (l >= 0 && l < SS) e = *(const float4*)&Er[(size_t)l * HD + dq];
                int d2 = dq >> 1;
                W2h[d2 * WP2 + tl]       = pkh(e.y, e.x);
                W2h[(d2 + 1) * WP2 + tl] = pkh(e.w, e.z);
            }
        }
        __syncthreads();

        // ---- transpose V into packed bf16 hi/lo planes [d][jpair] ----
        #pragma unroll
        for (int ii = 0; ii < 8; ii++) {
            int idx = tid + ii * 256;
            int jp = idx >> 6, d = idx & 63;
            float v0 = Vs[(2 * jp) * VP + d];
            float v1 = Vs[(2 * jp + 1) * VP + d];
            unsigned h = pk2(v1, v0);
            unsigned l = pk2(v1 - hi16f(h), v0 - lo16f(h));
            Vth[d * 36 + jp] = h;
            Vtl[d * 36 + jp] = l;
        }
        __syncthreads();

        // ---- S = Q K^T (fp16, 4 k16 steps x 8 n-blocks = 32 mma) ----
        float4 sacc[8];
        #pragma unroll
        for (int n = 0; n < 8; n++) {
            float4 c = make_float4(0.f, 0.f, 0.f, 0.f);
            #pragma unroll
            for (int s = 0; s < 4; s++) {
                unsigned b0 = Khs[(8 * s + t) * KP2 + 8 * n + g];
                unsigned b1 = Khs[(8 * s + t + 4) * KP2 + 8 * n + g];
                mmah(c, aq[s][0], aq[s][1], aq[s][2], aq[s][3], b0, b1);
            }
            sacc[n] = c;
        }

        const bool wneed1 = (j0 <= i0 + rbase + 15);
        const bool wneed2 = (j0 + 63 >= i0 + rbase + 2);

        // ---- case-1 relative term (fp16, 40 mma) ----
        if (wneed1) {
            #pragma unroll
            for (int n = 0; n < 10; n++) {
                float4 c = make_float4(0.f, 0.f, 0.f, 0.f);
                #pragma unroll
                for (int s = 0; s < 4; s++) {
                    unsigned b0 = W1h[(8 * s + t) * WP2 + off1w + 8 * n + g];
                    unsigned b1 = W1h[(8 * s + t + 4) * WP2 + off1w + 8 * n + g];
                    mmah(c, aq[s][0], aq[s][1], aq[s][2], aq[s][3], b0, b1);
                }
                wr0[8 * n] = c.x; wr0[8 * n + 1] = c.y;
                wr1[8 * n] = c.z; wr1[8 * n + 1] = c.w;
            }
            __syncwarp();
            #pragma unroll
            for (int n = 0; n < 8; n++) {
                int d00 = diffb + j0 + 8 * n;
                int tl = tlb + 8 * n;
                if (d00 <= 0)     sacc[n].x += rp0[tl];
                if (d00 + 1 <= 0) sacc[n].y += rp0[tl + 1];
                if (d00 - 8 <= 0) sacc[n].z += rp1[tl - 8];
                if (d00 - 7 <= 0) sacc[n].w += rp1[tl - 7];
            }
            __syncwarp();
        }
        // ---- case-2 relative term (fp16, 40 mma) ----
        if (wneed2) {
            #pragma unroll
            for (int n = 0; n < 10; n++) {
                float4 c = make_float4(0.f, 0.f, 0.f, 0.f);
                #pragma unroll
                for (int s = 0; s < 4; s++) {
                    unsigned b0 = W2h[(8 * s + t) * WP2 + off1w + 8 * n + g];
                    unsigned b1 = W2h[(8 * s + t + 4) * WP2 + off1w + 8 * n + g];
                    mmah(c, aq2[s][0], aq2[s][1], aq2[s][2], aq2[s][3], b0, b1);
                }
                wr0[8 * n] = c.x; wr0[8 * n + 1] = c.y;
                wr1[8 * n] = c.z; wr1[8 * n + 1] = c.w;
            }
            __syncwarp();
            #pragma unroll
            for (int n = 0; n < 8; n++) {
                int d00 = diffb + j0 + 8 * n;
                int tl = tlb + 8 * n;
                if (d00 >= 2)     sacc[n].x += rp0[tl];
                if (d00 + 1 >= 2) sacc[n].y += rp0[tl + 1];
                if (d00 - 8 >= 2) sacc[n].z += rp1[tl - 8];
                if (d00 - 7 >= 2) sacc[n].w += rp1[tl - 7];
            }
            __syncwarp();
        }

        // ---- scale + online softmax ----
        float mx0 = -1e30f, mx1 = -1e30f;
        #pragma unroll
        for (int n = 0; n < 8; n++) {
            sacc[n].x *= SCALE; sacc[n].y *= SCALE;
            sacc[n].z *= SCALE; sacc[n].w *= SCALE;
            mx0 = fmaxf(mx0, fmaxf(sacc[n].x, sacc[n].y));
            mx1 = fmaxf(mx1, fmaxf(sacc[n].z, sacc[n].w));
        }
        #pragma unroll
        for (int off = 1; off <= 2; off <<= 1) {
            mx0 = fmaxf(mx0, __shfl_xor_sync(0xffffffffu, mx0, off));
            mx1 = fmaxf(mx1, __shfl_xor_sync(0xffffffffu, mx1, off));
        }
        float mn0 = fmaxf(m0r, mx0), mn1 = fmaxf(m1r, mx1);
        float c0 = __expf(m0r - mn0), c1 = __expf(m1r - mn1);
        float rs0 = 0.f, rs1 = 0.f;
        #pragma unroll
        for (int n = 0; n < 8; n++) {
            sacc[n].x = __expf(sacc[n].x - mn0);
            sacc[n].y = __expf(sacc[n].y - mn0);
            sacc[n].z = __expf(sacc[n].z - mn1);
            sacc[n].w = __expf(sacc[n].w - mn1);
            rs0 += sacc[n].x + sacc[n].y;
            rs1 += sacc[n].z + sacc[n].w;
        }
        #pragma unroll
        for (int off = 1; off <= 2; off <<= 1) {
            rs0 += __shfl_xor_sync(0xffffffffu, rs0, off);
            rs1 += __shfl_xor_sync(0xffffffffu, rs1, off);
        }
        l0r = l0r * c0 + rs0;  m0r = mn0;
        l1r = l1r * c1 + rs1;  m1r = mn1;
        #pragma unroll
        for (int n = 0; n < 8; n++) {
            Oacc[n].x *= c0; Oacc[n].y *= c0;
            Oacc[n].z *= c1; Oacc[n].w *= c1;
        }

        // ---- O += P V  (bf16 3-pass; A-frags straight from sacc) ----
        #pragma unroll
        for (int sp = 0; sp < 4; sp++) {
            float4 pa = sacc[2 * sp], pb = sacc[2 * sp + 1];
            unsigned ah0 = pk2(pa.y, pa.x), ah1 = pk2(pa.w, pa.z);
            unsigned ah2 = pk2(pb.y, pb.x), ah3 = pk2(pb.w, pb.z);
            unsigned al0 = pk2(pa.y - hi16f(ah0), pa.x - lo16f(ah0));
            unsigned al1 = pk2(pa.w - hi16f(ah1), pa.z - lo16f(ah1));
            unsigned al2 = pk2(pb.y - hi16f(ah2), pb.x - lo16f(ah2));
            unsigned al3 = pk2(pb.w - hi16f(ah3), pb.z - lo16f(ah3));
            #pragma unroll
            for (int np = 0; np < 8; np++) {
                unsigned bh0 = Vth[(8 * np + g) * 36 + 8 * sp + t];
                unsigned bh1 = Vth[(8 * np + g) * 36 + 8 * sp + t + 4];
                unsigned bl0 = Vtl[(8 * np + g) * 36 + 8 * sp + t];
                unsigned bl1 = Vtl[(8 * np + g) * 36 + 8 * sp + t + 4];
                mma16(Oacc[np], ah0, ah1, ah2, ah3, bh0, bh1);
                mma16(Oacc[np], ah0, ah1, ah2, ah3, bl0, bl1);
                mma16(Oacc[np], al0, al1, al2, al3, bh0, bh1);
            }
        }
    }

    // ---- normalize + write out [b][s][h*64+d] ----
    const int b_ = bh >> 3, h = bh & 7;
    const float inv0 = 1.0f / l0r, inv1 = 1.0f / l1r;
    float* op0 = out + ((size_t)b_ * SS + (i0 + rbase + g)) * EE + h * HD;
    float* op1 = out + ((size_t)b_ * SS + (i0 + rbase + g + 8)) * EE + h * HD;
    #pragma unroll
    for (int n = 0; n < 8; n++) {
        *(float2*)&op0[8 * n + 2 * t] = make_float2(Oacc[n].x * inv0, Oacc[n].y * inv0);
        *(float2*)&op1[8 * n + 2 * t] = make_float2(Oacc[n].z * inv1, Oacc[n].w * inv1);
    }
}

// ---------------------------------------------------------------------------
// Kernel 3: in-place LayerNorm over E=512 per (b,s) row.
// ---------------------------------------------------------------------------
__global__ void __launch_bounds__(256) ln_kernel(
    float* __restrict__ out,
    const float* __restrict__ gamma,
    const float* __restrict__ beta)
{
    __shared__ float red[16];
    const int row = blockIdx.x;
    float* p = out + (size_t)row * EE;
    const int tid = threadIdx.x;

    float v0 = p[tid], v1 = p[tid + 256];
    float s = v0 + v1;
    float q = v0 * v0 + v1 * v1;
    #pragma unroll
    for (int off = 16; off > 0; off >>= 1) {
        s += __shfl_xor_sync(0xffffffffu, s, off);
        q += __shfl_xor_sync(0xffffffffu, q, off);
    }
    const int wid = tid >> 5, lid = tid & 31;
    if (lid == 0) { red[wid] = s; red[8 + wid] = q; }
    __syncthreads();
    s = 0.0f; q = 0.0f;
    #pragma unroll
    for (int w = 0; w < 8; w++) { s += red[w]; q += red[8 + w]; }

    float mu = s * (1.0f / EE);
    float var = q * (1.0f / EE) - mu * mu;
    float inv = rsqrtf(var + 1e-5f);
    p[tid]       = (v0 - mu) * inv * gamma[tid]       + beta[tid];
    p[tid + 256] = (v1 - mu) * inv * gamma[tid + 256] + beta[tid + 256];
}

// ---------------------------------------------------------------------------
extern "C" void kernel_launch(void* const* d_in, const int* in_sizes, int n_in,
                              void* d_out, int out_size)
{
    const float* x     = (const float*)d_in[0];
    const float* Wq    = (const float*)d_in[1];
    const float* Wk    = (const float*)d_in[2];
    const float* Wv    = (const float*)d_in[3];
    const float* Er    = (const float*)d_in[4];
    const float* gamma = (const float*)d_in[5];
    const float* beta  = (const float*)d_in[6];
    float* out = (float*)d_out;

    cudaFuncSetAttribute(qkv_mma_kernel,
                         cudaFuncAttributeMaxDynamicSharedMemorySize, QKV_SMEM_BYTES);
    cudaFuncSetAttribute(attn_kernel,
                         cudaFuncAttributeMaxDynamicSharedMemorySize, SMEM_BYTES);

    qkv_mma_kernel<<<dim3(EE / 128, (BB * SS) / 128, 3), 256, QKV_SMEM_BYTES>>>(x, Wq, Wk, Wv);
    attn_kernel<<<dim3(SS / 128, BB * HH), 256, SMEM_BYTES>>>(Er, out);
    ln_kernel<<<BB * SS, 256>>>(out, gamma, beta);
}

// round 7
// speedup vs baseline: 1.5071x; 1.5071x over previous
#include <cuda_runtime.h>
#include <math.h>

#define BB 4
#define SS 2048
#define EE 512
#define HH 8
#define HD 64
#define SCALE 0.04419417382415922f  /* 512^-0.5 (reference scales by E, not HD) */

// Scratch (static device arrays — allocation rules forbid cudaMalloc)
__device__ float g_q[BB * HH * SS * HD];
__device__ float g_k[BB * HH * SS * HD];
__device__ float g_v[BB * HH * SS * HD];

// ---------------------------------------------------------------------------
// helpers
// ---------------------------------------------------------------------------
// pack {upper=hi, lower=lo} bf16x2
__device__ __forceinline__ unsigned pk2(float hi, float lo) {
    unsigned r; asm("cvt.rn.bf16x2.f32 %0, %1, %2;" : "=r"(r) : "f"(hi), "f"(lo)); return r;
}
__device__ __forceinline__ float lo16f(unsigned u) { return __uint_as_float(u << 16); }
__device__ __forceinline__ float hi16f(unsigned u) { return __uint_as_float(u & 0xffff0000u); }

// bf16 m16n8k16 (measured ~32 cyc/SMSP on sm_103a — same as tf32 k8, 2x MACs)
__device__ __forceinline__ void mma16(float4& c,
    unsigned a0, unsigned a1, unsigned a2, unsigned a3, unsigned b0, unsigned b1)
{
    asm("mma.sync.aligned.m16n8k16.row.col.f32.bf16.bf16.f32 "
        "{%0,%1,%2,%3}, {%4,%5,%6,%7}, {%8,%9}, {%0,%1,%2,%3};"
        : "+f"(c.x), "+f"(c.y), "+f"(c.z), "+f"(c.w)
        : "r"(a0), "r"(a1), "r"(a2), "r"(a3), "r"(b0), "r"(b1));
}
__device__ __forceinline__ void cpa16(float* dst, const float* src) {
    unsigned sa = (unsigned)__cvta_generic_to_shared(dst);
    asm volatile("cp.async.cg.shared.global [%0], [%1], 16;" :: "r"(sa), "l"(src));
}
#define CP_COMMIT() asm volatile("cp.async.commit_group;")
#define CP_WAIT(n)  asm volatile("cp.async.wait_group %0;" :: "n"(n))

// ---------------------------------------------------------------------------
// Kernel 1: QKV projection.
//   z=0/1 (Q/K): bf16 single-pass m16n8k16 (score-path error budget allows).
//   z=2 (V): bf16 3-pass split (errors hit output linearly; keep exact).
// CTA 128x128, 8 warps, warp 64x32, K=32 panels double-buffered cp.async.
// ---------------------------------------------------------------------------
#define QKV_SMEM_BYTES (18432 * 4)

__global__ void __launch_bounds__(256, 1) qkv_mma_kernel(
    const float* __restrict__ x, const float* __restrict__ Wq,
    const float* __restrict__ Wk, const float* __restrict__ Wv)
{
    extern __shared__ float sm[];
    const int z = blockIdx.z;
    const float* W = z == 0 ? Wq : (z == 1 ? Wk : Wv);
    float* outp = z == 0 ? g_q : (z == 1 ? g_k : g_v);
    const int m0 = blockIdx.y * 128, n0 = blockIdx.x * 128;
    const int tid = threadIdx.x, lane = tid & 31, warp = tid >> 5;
    const int g = lane >> 2, t = lane & 3;
    const int mw = (warp >> 2) * 64, nw = (warp & 3) * 32;

    float* Xs[2] = { sm, sm + 4608 };
    float* Ws[2] = { sm + 9216, sm + 13824 };
    const int r_ = tid >> 1, c_ = (tid & 1) * 16;
    #define STAGE(buf, k0) do { \
        cpa16(Xs[buf] + r_ * 36 + c_,      &x[(size_t)(m0 + r_) * EE + (k0) + c_]); \
        cpa16(Xs[buf] + r_ * 36 + c_ + 4,  &x[(size_t)(m0 + r_) * EE + (k0) + c_ + 4]); \
        cpa16(Xs[buf] + r_ * 36 + c_ + 8,  &x[(size_t)(m0 + r_) * EE + (k0) + c_ + 8]); \
        cpa16(Xs[buf] + r_ * 36 + c_ + 12, &x[(size_t)(m0 + r_) * EE + (k0) + c_ + 12]); \
        cpa16(Ws[buf] + r_ * 36 + c_,      &W[(size_t)(n0 + r_) * EE + (k0) + c_]); \
        cpa16(Ws[buf] + r_ * 36 + c_ + 4,  &W[(size_t)(n0 + r_) * EE + (k0) + c_ + 4]); \
        cpa16(Ws[buf] + r_ * 36 + c_ + 8,  &W[(size_t)(n0 + r_) * EE + (k0) + c_ + 8]); \
        cpa16(Ws[buf] + r_ * 36 + c_ + 12, &W[(size_t)(n0 + r_) * EE + (k0) + c_ + 12]); \
        CP_COMMIT(); \
    } while (0)

    float4 acc[4][4];
    #pragma unroll
    for (int m = 0; m < 4; m++)
        #pragma unroll
        for (int n = 0; n < 4; n++) acc[m][n] = make_float4(0.f, 0.f, 0.f, 0.f);

    STAGE(0, 0);
    for (int p = 0; p < 16; p++) {
        if (p < 15) STAGE((p + 1) & 1, (p + 1) * 32);
        if (p < 15) { CP_WAIT(1); } else { CP_WAIT(0); }
        __syncthreads();
        const float* Xb = Xs[p & 1];
        const float* Wb = Ws[p & 1];

        if (z < 2) {
            // ---- bf16 single-pass: 2 k16 steps ----
            #pragma unroll
            for (int s = 0; s < 2; s++) {
                unsigned a[4][4], b[4][2];
                #pragma unroll
                for (int m = 0; m < 4; m++) {
                    const float* r0 = &Xb[(mw + 16 * m + g) * 36 + 16 * s];
                    const float* r1 = &Xb[(mw + 16 * m + g + 8) * 36 + 16 * s];
                    float2 f0 = *(const float2*)&r0[2 * t];
                    float2 f1 = *(const float2*)&r1[2 * t];
                    float2 f2 = *(const float2*)&r0[2 * t + 8];
                    float2 f3 = *(const float2*)&r1[2 * t + 8];
                    a[m][0] = pk2(f0.y, f0.x);
                    a[m][1] = pk2(f1.y, f1.x);
                    a[m][2] = pk2(f2.y, f2.x);
                    a[m][3] = pk2(f3.y, f3.x);
                }
                #pragma unroll
                for (int n = 0; n < 4; n++) {
                    const float* w0 = &Wb[(nw + 8 * n + g) * 36 + 16 * s];
                    float2 f0 = *(const float2*)&w0[2 * t];
                    float2 f1 = *(const float2*)&w0[2 * t + 8];
                    b[n][0] = pk2(f0.y, f0.x);
                    b[n][1] = pk2(f1.y, f1.x);
                }
                #pragma unroll
                for (int m = 0; m < 4; m++)
                    #pragma unroll
                    for (int n = 0; n < 4; n++)
                        mma16(acc[m][n], a[m][0], a[m][1], a[m][2], a[m][3], b[n][0], b[n][1]);
            }
        } else {
            // ---- bf16 3-pass split: 2 k16 steps ----
            #pragma unroll
            for (int s = 0; s < 2; s++) {
                unsigned ah[4][4], al[4][4], bh[4][2], bl[4][2];
                #pragma unroll
                for (int m = 0; m < 4; m++) {
                    const float* r0 = &Xb[(mw + 16 * m + g) * 36 + 16 * s];
                    const float* r1 = &Xb[(mw + 16 * m + g + 8) * 36 + 16 * s];
                    float2 f0 = *(const float2*)&r0[2 * t];
                    float2 f1 = *(const float2*)&r1[2 * t];
                    float2 f2 = *(const float2*)&r0[2 * t + 8];
                    float2 f3 = *(const float2*)&r1[2 * t + 8];
                    ah[m][0] = pk2(f0.y, f0.x); al[m][0] = pk2(f0.y - hi16f(ah[m][0]), f0.x - lo16f(ah[m][0]));
                    ah[m][1] = pk2(f1.y, f1.x); al[m][1] = pk2(f1.y - hi16f(ah[m][1]), f1.x - lo16f(ah[m][1]));
                    ah[m][2] = pk2(f2.y, f2.x); al[m][2] = pk2(f2.y - hi16f(ah[m][2]), f2.x - lo16f(ah[m][2]));
                    ah[m][3] = pk2(f3.y, f3.x); al[m][3] = pk2(f3.y - hi16f(ah[m][3]), f3.x - lo16f(ah[m][3]));
                }
                #pragma unroll
                for (int n = 0; n < 4; n++) {
                    const float* w0 = &Wb[(nw + 8 * n + g) * 36 + 16 * s];
                    float2 f0 = *(const float2*)&w0[2 * t];
                    float2 f1 = *(const float2*)&w0[2 * t + 8];
                    bh[n][0] = pk2(f0.y, f0.x); bl[n][0] = pk2(f0.y - hi16f(bh[n][0]), f0.x - lo16f(bh[n][0]));
                    bh[n][1] = pk2(f1.y, f1.x); bl[n][1] = pk2(f1.y - hi16f(bh[n][1]), f1.x - lo16f(bh[n][1]));
                }
                #pragma unroll
                for (int m = 0; m < 4; m++)
                    #pragma unroll
                    for (int n = 0; n < 4; n++) {
                        mma16(acc[m][n], ah[m][0], ah[m][1], ah[m][2], ah[m][3], bh[n][0], bh[n][1]);
                        mma16(acc[m][n], ah[m][0], ah[m][1], ah[m][2], ah[m][3], bl[n][0], bl[n][1]);
                        mma16(acc[m][n], al[m][0], al[m][1], al[m][2], al[m][3], bh[n][0], bh[n][1]);
                    }
            }
        }
        __syncthreads();
    }

    #pragma unroll
    for (int m = 0; m < 4; m++) {
        int r0 = m0 + mw + 16 * m + g, r1 = r0 + 8;
        int b0_ = r0 >> 11, s0_ = r0 & 2047;
        int b1_ = r1 >> 11, s1_ = r1 & 2047;
        #pragma unroll
        for (int n = 0; n < 4; n++) {
            int col = n0 + nw + 8 * n + 2 * t;
            int h = col >> 6, d = col & 63;
            *(float2*)&outp[(((size_t)b0_ * HH + h) * SS + s0_) * HD + d] = make_float2(acc[m][n].x, acc[m][n].y);
            *(float2*)&outp[(((size_t)b1_ * HH + h) * SS + s1_) * HD + d] = make_float2(acc[m][n].z, acc[m][n].w);
        }
    }
}

// ---------------------------------------------------------------------------
// Kernel 2: flash attention with relative-position skew.
//
// Srel[i,j] = q_i . Er[S-1-(i-j)]  (j<=i) | 0 (j=i+1) | q_{i+1} . Er[j-i-2] (j>=i+2)
//
// S, R1, R2: bf16 m16n8k16 single-pass (32-cyc class, 2x MACs vs tf32-k8).
// PV: bf16 m16n8k16 3-pass split (A-frags straight from softmax accumulators).
// ---------------------------------------------------------------------------
#define QP 68
#define KP2 72     /* packed bf16x2 K^T rows: [32][72] */
#define VP 72
#define WP2 200    /* packed bf16x2 Er windows: [32][200] */
#define RP 84
#define SM_Q  0
#define SM_K  (129 * QP)              /* 8772  */
#define SM_V  (SM_K + 32 * KP2)       /* 11076 */
#define SM_W1 (SM_V + 64 * VP)        /* 15684 */
#define SM_W2 (SM_W1 + 32 * WP2)      /* 22084 */
#define SM_R  (SM_W2 + 32 * WP2)      /* 28484 */
#define SM_TOT_FLOATS (SM_R + 128 * RP)   /* 39236 */
#define SMEM_BYTES (SM_TOT_FLOATS * 4)

__global__ void __launch_bounds__(256, 1) attn_kernel(
    const float* __restrict__ Er, float* __restrict__ out)
{
    extern __shared__ float sm[];
    float* Qs   = sm + SM_Q;                 // [129][QP] fp32 Q rows (prologue only)
    unsigned* Khs = (unsigned*)(sm + SM_K);  // [32][KP2] bf16x2 K^T [d2][j]
    float* Vs   = sm + SM_V;                 // [64][VP]  fp32 V [j][d]
    unsigned* W1h = (unsigned*)(sm + SM_W1); // [32][WP2] bf16x2 Er window 1
    unsigned* W2h = (unsigned*)(sm + SM_W2); // [32][WP2] bf16x2 Er window 2
    float* Rscr = sm + SM_R;                 // [128][RP] per-warp R scratch
    unsigned* Vth = (unsigned*)sm;           // [64][36] bf16x2 hi (overlays Qs)
    unsigned* Vtl = ((unsigned*)sm) + 2304;  // [64][36] bf16x2 lo

    const int tid  = threadIdx.x;
    const int lane = tid & 31;
    const int warp = tid >> 5;
    const int g = lane >> 2;     // 0..7
    const int t = lane & 3;      // 0..3
    const int rbase = warp * 16;

    const int bh = blockIdx.y;
    const int i0 = blockIdx.x * 128;

    const float* qb0 = g_q + (size_t)bh * SS * HD;
    const float* kb0 = g_k + (size_t)bh * SS * HD;
    const float* vb0 = g_v + (size_t)bh * SS * HD;

    // ---- stage Q rows i0..i0+128 ----
    for (int idx = tid; idx < 129 * 16; idx += 256) {
        int r = idx >> 4, dq = (idx & 15) * 4;
        float4 v = make_float4(0.f, 0.f, 0.f, 0.f);
        int gi = i0 + r;
        if (gi < SS) v = *(const float4*)&qb0[(size_t)gi * HD + dq];
        *(float4*)&Qs[r * QP + dq] = v;
    }
    __syncthreads();

    // ---- resident A fragments (bf16, 4 k16 steps) ----
    unsigned aq[4][4], aq2[4][4];
    {
        const float* r0 = &Qs[(rbase + g) * QP];
        const float* r1 = &Qs[(rbase + g + 8) * QP];
        const float* s0 = &Qs[(rbase + g + 1) * QP];
        const float* s1 = &Qs[(rbase + g + 9) * QP];
        #pragma unroll
        for (int s = 0; s < 4; s++) {
            float2 f0 = *(const float2*)&r0[16 * s + 2 * t];
            float2 f1 = *(const float2*)&r1[16 * s + 2 * t];
            float2 f2 = *(const float2*)&r0[16 * s + 2 * t + 8];
            float2 f3 = *(const float2*)&r1[16 * s + 2 * t + 8];
            aq[s][0] = pk2(f0.y, f0.x);
            aq[s][1] = pk2(f1.y, f1.x);
            aq[s][2] = pk2(f2.y, f2.x);
            aq[s][3] = pk2(f3.y, f3.x);
            float2 h0 = *(const float2*)&s0[16 * s + 2 * t];
            float2 h1 = *(const float2*)&s1[16 * s + 2 * t];
            float2 h2 = *(const float2*)&s0[16 * s + 2 * t + 8];
            float2 h3 = *(const float2*)&s1[16 * s + 2 * t + 8];
            aq2[s][0] = pk2(h0.y, h0.x);
            aq2[s][1] = pk2(h1.y, h1.x);
            aq2[s][2] = pk2(h2.y, h2.x);
            aq2[s][3] = pk2(h3.y, h3.x);
        }
    }
    __syncthreads();  // frag build done before Vth overwrites Qs

    float4 Oacc[8];
    #pragma unroll
    for (int n = 0; n < 8; n++) Oacc[n] = make_float4(0.f, 0.f, 0.f, 0.f);
    float m0r = -1e30f, m1r = -1e30f, l0r = 0.f, l1r = 0.f;

    const float* rp0 = &Rscr[(rbase + g) * RP];
    const float* rp1 = &Rscr[(rbase + g + 8) * RP];
    float* wr0 = &Rscr[(rbase + g) * RP + 2 * t];
    float* wr1 = &Rscr[(rbase + g + 8) * RP + 2 * t];
    const int off1w = 112 - rbase;
    const int tlb = 2 * t + 15 - g;
    const int diffb = (2 * t) - (i0 + rbase + g);

    for (int j0 = 0; j0 < SS; j0 += 64) {
        __syncthreads();  // previous tile compute done before restage

        const bool need1 = (j0 <= i0 + 127);
        const bool need2 = (j0 + 63 >= i0 + 2);
        const int L1 = SS - 128 - i0 + j0;
        const int L2 = j0 - i0 - 129;

        // ---- stage K^T packed bf16x2 [d2][j], V fp32 ----
        for (int idx = tid; idx < 64 * 16; idx += 256) {
            int j = idx >> 4, dq = (idx & 15) * 4;
            float4 kv = *(const float4*)&kb0[(size_t)(j0 + j) * HD + dq];
            int d2 = dq >> 1;
            Khs[d2 * KP2 + j]       = pk2(kv.y, kv.x);
            Khs[(d2 + 1) * KP2 + j] = pk2(kv.w, kv.z);
            *(float4*)&Vs[j * VP + dq] = *(const float4*)&vb0[(size_t)(j0 + j) * HD + dq];
        }
        if (need1) {
            for (int idx = tid; idx < 192 * 16; idx += 256) {
                int tl = idx >> 4, dq = (idx & 15) * 4;
                int l = L1 + tl;
                float4 e = make_float4(0.f, 0.f, 0.f, 0.f);
                if (l >= 0 && l < SS) e = *(const float4*)&Er[(size_t)l * HD + dq];
                int d2 = dq >> 1;
                W1h[d2 * WP2 + tl]       = pk2(e.y, e.x);
                W1h[(d2 + 1) * WP2 + tl] = pk2(e.w, e.z);
            }
        }
        if (need2) {
            for (int idx = tid; idx < 192 * 16; idx += 256) {
                int tl = idx >> 4, dq = (idx & 15) * 4;
                int l = L2 + tl;
                float4 e = make_float4(0.f, 0.f, 0.f, 0.f);
                if (l >= 0 && l < SS) e = *(const float4*)&Er[(size_t)l * HD + dq];
                int d2 = dq >> 1;
                W2h[d2 * WP2 + tl]       = pk2(e.y, e.x);
                W2h[(d2 + 1) * WP2 + tl] = pk2(e.w, e.z);
            }
        }
        __syncthreads();

        // ---- transpose V into packed bf16 hi/lo planes [d][jpair] ----
        #pragma unroll
        for (int ii = 0; ii < 8; ii++) {
            int idx = tid + ii * 256;
            int jp = idx >> 6, d = idx & 63;
            float v0 = Vs[(2 * jp) * VP + d];
            float v1 = Vs[(2 * jp + 1) * VP + d];
            unsigned h = pk2(v1, v0);
            unsigned l = pk2(v1 - hi16f(h), v0 - lo16f(h));
            Vth[d * 36 + jp] = h;
            Vtl[d * 36 + jp] = l;
        }
        __syncthreads();

        // ---- S = Q K^T (bf16, 4 k16 steps x 8 n-blocks = 32 mma) ----
        float4 sacc[8];
        #pragma unroll
        for (int n = 0; n < 8; n++) {
            float4 c = make_float4(0.f, 0.f, 0.f, 0.f);
            #pragma unroll
            for (int s = 0; s < 4; s++) {
                unsigned b0 = Khs[(8 * s + t) * KP2 + 8 * n + g];
                unsigned b1 = Khs[(8 * s + t + 4) * KP2 + 8 * n + g];
                mma16(c, aq[s][0], aq[s][1], aq[s][2], aq[s][3], b0, b1);
            }
            sacc[n] = c;
        }

        const bool wneed1 = (j0 <= i0 + rbase + 15);
        const bool wneed2 = (j0 + 63 >= i0 + rbase + 2);

        // ---- case-1 relative term (bf16, 40 mma) ----
        if (wneed1) {
            #pragma unroll
            for (int n = 0; n < 10; n++) {
                float4 c = make_float4(0.f, 0.f, 0.f, 0.f);
                #pragma unroll
                for (int s = 0; s < 4; s++) {
                    unsigned b0 = W1h[(8 * s + t) * WP2 + off1w + 8 * n + g];
                    unsigned b1 = W1h[(8 * s + t + 4) * WP2 + off1w + 8 * n + g];
                    mma16(c, aq[s][0], aq[s][1], aq[s][2], aq[s][3], b0, b1);
                }
                wr0[8 * n] = c.x; wr0[8 * n + 1] = c.y;
                wr1[8 * n] = c.z; wr1[8 * n + 1] = c.w;
            }
            __syncwarp();
            #pragma unroll
            for (int n = 0; n < 8; n++) {
                int d00 = diffb + j0 + 8 * n;
                int tl = tlb + 8 * n;
                if (d00 <= 0)     sacc[n].x += rp0[tl];
                if (d00 + 1 <= 0) sacc[n].y += rp0[tl + 1];
                if (d00 - 8 <= 0) sacc[n].z += rp1[tl - 8];
                if (d00 - 7 <= 0) sacc[n].w += rp1[tl - 7];
            }
            __syncwarp();
        }
        // ---- case-2 relative term (bf16, 40 mma) ----
        if (wneed2) {
            #pragma unroll
            for (int n = 0; n < 10; n++) {
                float4 c = make_float4(0.f, 0.f, 0.f, 0.f);
                #pragma unroll
                for (int s = 0; s < 4; s++) {
                    unsigned b0 = W2h[(8 * s + t) * WP2 + off1w + 8 * n + g];
                    unsigned b1 = W2h[(8 * s + t + 4) * WP2 + off1w + 8 * n + g];
                    mma16(c, aq2[s][0], aq2[s][1], aq2[s][2], aq2[s][3], b0, b1);
                }
                wr0[8 * n] = c.x; wr0[8 * n + 1] = c.y;
                wr1[8 * n] = c.z; wr1[8 * n + 1] = c.w;
            }
            __syncwarp();
            #pragma unroll
            for (int n = 0; n < 8; n++) {
                int d00 = diffb + j0 + 8 * n;
                int tl = tlb + 8 * n;
                if (d00 >= 2)     sacc[n].x += rp0[tl];
                if (d00 + 1 >= 2) sacc[n].y += rp0[tl + 1];
                if (d00 - 8 >= 2) sacc[n].z += rp1[tl - 8];
                if (d00 - 7 >= 2) sacc[n].w += rp1[tl - 7];
            }
            __syncwarp();
        }

        // ---- scale + online softmax ----
        float mx0 = -1e30f, mx1 = -1e30f;
        #pragma unroll
        for (int n = 0; n < 8; n++) {
            sacc[n].x *= SCALE; sacc[n].y *= SCALE;
            sacc[n].z *= SCALE; sacc[n].w *= SCALE;
            mx0 = fmaxf(mx0, fmaxf(sacc[n].x, sacc[n].y));
            mx1 = fmaxf(mx1, fmaxf(sacc[n].z, sacc[n].w));
        }
        #pragma unroll
        for (int off = 1; off <= 2; off <<= 1) {
            mx0 = fmaxf(mx0, __shfl_xor_sync(0xffffffffu, mx0, off));
            mx1 = fmaxf(mx1, __shfl_xor_sync(0xffffffffu, mx1, off));
        }
        float mn0 = fmaxf(m0r, mx0), mn1 = fmaxf(m1r, mx1);
        float c0 = __expf(m0r - mn0), c1 = __expf(m1r - mn1);
        float rs0 = 0.f, rs1 = 0.f;
        #pragma unroll
        for (int n = 0; n < 8; n++) {
            sacc[n].x = __expf(sacc[n].x - mn0);
            sacc[n].y = __expf(sacc[n].y - mn0);
            sacc[n].z = __expf(sacc[n].z - mn1);
            sacc[n].w = __expf(sacc[n].w - mn1);
            rs0 += sacc[n].x + sacc[n].y;
            rs1 += sacc[n].z + sacc[n].w;
        }
        #pragma unroll
        for (int off = 1; off <= 2; off <<= 1) {
            rs0 += __shfl_xor_sync(0xffffffffu, rs0, off);
            rs1 += __shfl_xor_sync(0xffffffffu, rs1, off);
        }
        l0r = l0r * c0 + rs0;  m0r = mn0;
        l1r = l1r * c1 + rs1;  m1r = mn1;
        #pragma unroll
        for (int n = 0; n < 8; n++) {
            Oacc[n].x *= c0; Oacc[n].y *= c0;
            Oacc[n].z *= c1; Oacc[n].w *= c1;
        }

        // ---- O += P V  (bf16 3-pass; A-frags straight from sacc) ----
        #pragma unroll
        for (int sp = 0; sp < 4; sp++) {
            float4 pa = sacc[2 * sp], pb = sacc[2 * sp + 1];
            unsigned ah0 = pk2(pa.y, pa.x), ah1 = pk2(pa.w, pa.z);
            unsigned ah2 = pk2(pb.y, pb.x), ah3 = pk2(pb.w, pb.z);
            unsigned al0 = pk2(pa.y - hi16f(ah0), pa.x - lo16f(ah0));
            unsigned al1 = pk2(pa.w - hi16f(ah1), pa.z - lo16f(ah1));
            unsigned al2 = pk2(pb.y - hi16f(ah2), pb.x - lo16f(ah2));
            unsigned al3 = pk2(pb.w - hi16f(ah3), pb.z - lo16f(ah3));
            #pragma unroll
            for (int np = 0; np < 8; np++) {
                unsigned bh0 = Vth[(8 * np + g) * 36 + 8 * sp + t];
                unsigned bh1 = Vth[(8 * np + g) * 36 + 8 * sp + t + 4];
                unsigned bl0 = Vtl[(8 * np + g) * 36 + 8 * sp + t];
                unsigned bl1 = Vtl[(8 * np + g) * 36 + 8 * sp + t + 4];
                mma16(Oacc[np], ah0, ah1, ah2, ah3, bh0, bh1);
                mma16(Oacc[np], ah0, ah1, ah2, ah3, bl0, bl1);
                mma16(Oacc[np], al0, al1, al2, al3, bh0, bh1);
            }
        }
    }

    // ---- normalize + write out [b][s][h*64+d] ----
    const int b_ = bh >> 3, h = bh & 7;
    const float inv0 = 1.0f / l0r, inv1 = 1.0f / l1r;
    float* op0 = out + ((size_t)b_ * SS + (i0 + rbase + g)) * EE + h * HD;
    float* op1 = out + ((size_t)b_ * SS + (i0 + rbase + g + 8)) * EE + h * HD;
    #pragma unroll
    for (int n = 0; n < 8; n++) {
        *(float2*)&op0[8 * n + 2 * t] = make_float2(Oacc[n].x * inv0, Oacc[n].y * inv0);
        *(float2*)&op1[8 * n + 2 * t] = make_float2(Oacc[n].z * inv1, Oacc[n].w * inv1);
    }
}

// ---------------------------------------------------------------------------
// Kernel 3: in-place LayerNorm over E=512 per (b,s) row.
// ---------------------------------------------------------------------------
__global__ void __launch_bounds__(256) ln_kernel(
    float* __restrict__ out,
    const float* __restrict__ gamma,
    const float* __restrict__ beta)
{
    __shared__ float red[16];
    const int row = blockIdx.x;
    float* p = out + (size_t)row * EE;
    const int tid = threadIdx.x;

    float v0 = p[tid], v1 = p[tid + 256];
    float s = v0 + v1;
    float q = v0 * v0 + v1 * v1;
    #pragma unroll
    for (int off = 16; off > 0; off >>= 1) {
        s += __shfl_xor_sync(0xffffffffu, s, off);
        q += __shfl_xor_sync(0xffffffffu, q, off);
    }
    const int wid = tid >> 5, lid = tid & 31;
    if (lid == 0) { red[wid] = s; red[8 + wid] = q; }
    __syncthreads();
    s = 0.0f; q = 0.0f;
    #pragma unroll
    for (int w = 0; w < 8; w++) { s += red[w]; q += red[8 + w]; }

    float mu = s * (1.0f / EE);
    float var = q * (1.0f / EE) - mu * mu;
    float inv = rsqrtf(var + 1e-5f);
    p[tid]       = (v0 - mu) * inv * gamma[tid]       + beta[tid];
    p[tid + 256] = (v1 - mu) * inv * gamma[tid + 256] + beta[tid + 256];
}

// ---------------------------------------------------------------------------
extern "C" void kernel_launch(void* const* d_in, const int* in_sizes, int n_in,
                              void* d_out, int out_size)
{
    const float* x     = (const float*)d_in[0];
    const float* Wq    = (const float*)d_in[1];
    const float* Wk    = (const float*)d_in[2];
    const float* Wv    = (const float*)d_in[3];
    const float* Er    = (const float*)d_in[4];
    const float* gamma = (const float*)d_in[5];
    const float* beta  = (const float*)d_in[6];
    float* out = (float*)d_out;

    cudaFuncSetAttribute(qkv_mma_kernel,
                         cudaFuncAttributeMaxDynamicSharedMemorySize, QKV_SMEM_BYTES);
    cudaFuncSetAttribute(attn_kernel,
                         cudaFuncAttributeMaxDynamicSharedMemorySize, SMEM_BYTES);

    qkv_mma_kernel<<<dim3(EE / 128, (BB * SS) / 128, 3), 256, QKV_SMEM_BYTES>>>(x, Wq, Wk, Wv);
    attn_kernel<<<dim3(SS / 128, BB * HH), 256, SMEM_BYTES>>>(Er, out);
    ln_kernel<<<BB * SS, 256>>>(out, gamma, beta);
}

// round 8
// speedup vs baseline: 1.5390x; 1.0212x over previous
#include <cuda_runtime.h>
#include <math.h>

#define BB 4
#define SS 2048
#define EE 512
#define HH 8
#define HD 64
#define SCALE 0.04419417382415922f  /* 512^-0.5 (reference scales by E, not HD) */

// Scratch (static device arrays — allocation rules forbid cudaMalloc)
__device__ float g_q[BB * HH * SS * HD];
__device__ float g_k[BB * HH * SS * HD];
__device__ float g_v[BB * HH * SS * HD];

// ---------------------------------------------------------------------------
// helpers
// ---------------------------------------------------------------------------
__device__ __forceinline__ unsigned f2tf(float x) {
    unsigned r; asm("cvt.rna.tf32.f32 %0, %1;" : "=r"(r) : "f"(x)); return r;
}
// pack {upper=hi, lower=lo} bf16x2
__device__ __forceinline__ unsigned pk2(float hi, float lo) {
    unsigned r; asm("cvt.rn.bf16x2.f32 %0, %1, %2;" : "=r"(r) : "f"(hi), "f"(lo)); return r;
}
__device__ __forceinline__ float lo16f(unsigned u) { return __uint_as_float(u << 16); }
__device__ __forceinline__ float hi16f(unsigned u) { return __uint_as_float(u & 0xffff0000u); }

// tf32 m16n8k8 (~32 cyc/SMSP)
__device__ __forceinline__ void mma8(float4& c,
    unsigned a0, unsigned a1, unsigned a2, unsigned a3, unsigned b0, unsigned b1)
{
    asm("mma.sync.aligned.m16n8k8.row.col.f32.tf32.tf32.f32 "
        "{%0,%1,%2,%3}, {%4,%5,%6,%7}, {%8,%9}, {%0,%1,%2,%3};"
        : "+f"(c.x), "+f"(c.y), "+f"(c.z), "+f"(c.w)
        : "r"(a0), "r"(a1), "r"(a2), "r"(a3), "r"(b0), "r"(b1));
}
// bf16 m16n8k16 (~32 cyc/SMSP — same as tf32-k8, 2x MACs)
__device__ __forceinline__ void mma16(float4& c,
    unsigned a0, unsigned a1, unsigned a2, unsigned a3, unsigned b0, unsigned b1)
{
    asm("mma.sync.aligned.m16n8k16.row.col.f32.bf16.bf16.f32 "
        "{%0,%1,%2,%3}, {%4,%5,%6,%7}, {%8,%9}, {%0,%1,%2,%3};"
        : "+f"(c.x), "+f"(c.y), "+f"(c.z), "+f"(c.w)
        : "r"(a0), "r"(a1), "r"(a2), "r"(a3), "r"(b0), "r"(b1));
}
__device__ __forceinline__ void cpa16(float* dst, const float* src) {
    unsigned sa = (unsigned)__cvta_generic_to_shared(dst);
    asm volatile("cp.async.cg.shared.global [%0], [%1], 16;" :: "r"(sa), "l"(src));
}
#define CP_COMMIT() asm volatile("cp.async.commit_group;")
#define CP_WAIT(n)  asm volatile("cp.async.wait_group %0;" :: "n"(n))

// ---------------------------------------------------------------------------
// Kernel 1: QKV projection.
//   z=0/1 (Q/K): tf32 single-pass m16n8k8 (latency-bound; precision is free).
//   z=2 (V): bf16 3-pass split (errors hit output linearly; keep ~fp32).
// CTA 128x128, 8 warps, warp 64x32, K=32 panels double-buffered cp.async.
// ---------------------------------------------------------------------------
#define QKV_SMEM_BYTES (18432 * 4)

__global__ void __launch_bounds__(256, 1) qkv_mma_kernel(
    const float* __restrict__ x, const float* __restrict__ Wq,
    const float* __restrict__ Wk, const float* __restrict__ Wv)
{
    extern __shared__ float sm[];
    const int z = blockIdx.z;
    const float* W = z == 0 ? Wq : (z == 1 ? Wk : Wv);
    float* outp = z == 0 ? g_q : (z == 1 ? g_k : g_v);
    const int m0 = blockIdx.y * 128, n0 = blockIdx.x * 128;
    const int tid = threadIdx.x, lane = tid & 31, warp = tid >> 5;
    const int g = lane >> 2, t = lane & 3;
    const int mw = (warp >> 2) * 64, nw = (warp & 3) * 32;

    float* Xs[2] = { sm, sm + 4608 };
    float* Ws[2] = { sm + 9216, sm + 13824 };
    const int r_ = tid >> 1, c_ = (tid & 1) * 16;
    #define STAGE(buf, k0) do { \
        cpa16(Xs[buf] + r_ * 36 + c_,      &x[(size_t)(m0 + r_) * EE + (k0) + c_]); \
        cpa16(Xs[buf] + r_ * 36 + c_ + 4,  &x[(size_t)(m0 + r_) * EE + (k0) + c_ + 4]); \
        cpa16(Xs[buf] + r_ * 36 + c_ + 8,  &x[(size_t)(m0 + r_) * EE + (k0) + c_ + 8]); \
        cpa16(Xs[buf] + r_ * 36 + c_ + 12, &x[(size_t)(m0 + r_) * EE + (k0) + c_ + 12]); \
        cpa16(Ws[buf] + r_ * 36 + c_,      &W[(size_t)(n0 + r_) * EE + (k0) + c_]); \
        cpa16(Ws[buf] + r_ * 36 + c_ + 4,  &W[(size_t)(n0 + r_) * EE + (k0) + c_ + 4]); \
        cpa16(Ws[buf] + r_ * 36 + c_ + 8,  &W[(size_t)(n0 + r_) * EE + (k0) + c_ + 8]); \
        cpa16(Ws[buf] + r_ * 36 + c_ + 12, &W[(size_t)(n0 + r_) * EE + (k0) + c_ + 12]); \
        CP_COMMIT(); \
    } while (0)

    float4 acc[4][4];
    #pragma unroll
    for (int m = 0; m < 4; m++)
        #pragma unroll
        for (int n = 0; n < 4; n++) acc[m][n] = make_float4(0.f, 0.f, 0.f, 0.f);

    STAGE(0, 0);
    for (int p = 0; p < 16; p++) {
        if (p < 15) STAGE((p + 1) & 1, (p + 1) * 32);
        if (p < 15) { CP_WAIT(1); } else { CP_WAIT(0); }
        __syncthreads();
        const float* Xb = Xs[p & 1];
        const float* Wb = Ws[p & 1];

        if (z < 2) {
            // ---- tf32 single-pass: 4 k8 steps ----
            #pragma unroll
            for (int s = 0; s < 4; s++) {
                unsigned a[4][4], b[4][2];
                #pragma unroll
                for (int m = 0; m < 4; m++) {
                    const float* r0 = &Xb[(mw + 16 * m + g) * 36 + 8 * s];
                    const float* r1 = &Xb[(mw + 16 * m + g + 8) * 36 + 8 * s];
                    a[m][0] = f2tf(r0[t]); a[m][1] = f2tf(r1[t]);
                    a[m][2] = f2tf(r0[t + 4]); a[m][3] = f2tf(r1[t + 4]);
                }
                #pragma unroll
                for (int n = 0; n < 4; n++) {
                    const float* w0 = &Wb[(nw + 8 * n + g) * 36 + 8 * s];
                    b[n][0] = f2tf(w0[t]); b[n][1] = f2tf(w0[t + 4]);
                }
                #pragma unroll
                for (int m = 0; m < 4; m++)
                    #pragma unroll
                    for (int n = 0; n < 4; n++)
                        mma8(acc[m][n], a[m][0], a[m][1], a[m][2], a[m][3], b[n][0], b[n][1]);
            }
        } else {
            // ---- bf16 3-pass split: 2 k16 steps ----
            #pragma unroll
            for (int s = 0; s < 2; s++) {
                unsigned ah[4][4], al[4][4], bh[4][2], bl[4][2];
                #pragma unroll
                for (int m = 0; m < 4; m++) {
                    const float* r0 = &Xb[(mw + 16 * m + g) * 36 + 16 * s];
                    const float* r1 = &Xb[(mw + 16 * m + g + 8) * 36 + 16 * s];
                    float2 f0 = *(const float2*)&r0[2 * t];
                    float2 f1 = *(const float2*)&r1[2 * t];
                    float2 f2 = *(const float2*)&r0[2 * t + 8];
                    float2 f3 = *(const float2*)&r1[2 * t + 8];
                    ah[m][0] = pk2(f0.y, f0.x); al[m][0] = pk2(f0.y - hi16f(ah[m][0]), f0.x - lo16f(ah[m][0]));
                    ah[m][1] = pk2(f1.y, f1.x); al[m][1] = pk2(f1.y - hi16f(ah[m][1]), f1.x - lo16f(ah[m][1]));
                    ah[m][2] = pk2(f2.y, f2.x); al[m][2] = pk2(f2.y - hi16f(ah[m][2]), f2.x - lo16f(ah[m][2]));
                    ah[m][3] = pk2(f3.y, f3.x); al[m][3] = pk2(f3.y - hi16f(ah[m][3]), f3.x - lo16f(ah[m][3]));
                }
                #pragma unroll
                for (int n = 0; n < 4; n++) {
                    const float* w0 = &Wb[(nw + 8 * n + g) * 36 + 16 * s];
                    float2 f0 = *(const float2*)&w0[2 * t];
                    float2 f1 = *(const float2*)&w0[2 * t + 8];
                    bh[n][0] = pk2(f0.y, f0.x); bl[n][0] = pk2(f0.y - hi16f(bh[n][0]), f0.x - lo16f(bh[n][0]));
                    bh[n][1] = pk2(f1.y, f1.x); bl[n][1] = pk2(f1.y - hi16f(bh[n][1]), f1.x - lo16f(bh[n][1]));
                }
                #pragma unroll
                for (int m = 0; m < 4; m++)
                    #pragma unroll
                    for (int n = 0; n < 4; n++) {
                        mma16(acc[m][n], ah[m][0], ah[m][1], ah[m][2], ah[m][3], bh[n][0], bh[n][1]);
                        mma16(acc[m][n], ah[m][0], ah[m][1], ah[m][2], ah[m][3], bl[n][0], bl[n][1]);
                        mma16(acc[m][n], al[m][0], al[m][1], al[m][2], al[m][3], bh[n][0], bh[n][1]);
                    }
            }
        }
        __syncthreads();
    }

    #pragma unroll
    for (int m = 0; m < 4; m++) {
        int r0 = m0 + mw + 16 * m + g, r1 = r0 + 8;
        int b0_ = r0 >> 11, s0_ = r0 & 2047;
        int b1_ = r1 >> 11, s1_ = r1 & 2047;
        #pragma unroll
        for (int n = 0; n < 4; n++) {
            int col = n0 + nw + 8 * n + 2 * t;
            int h = col >> 6, d = col & 63;
            *(float2*)&outp[(((size_t)b0_ * HH + h) * SS + s0_) * HD + d] = make_float2(acc[m][n].x, acc[m][n].y);
            *(float2*)&outp[(((size_t)b1_ * HH + h) * SS + s1_) * HD + d] = make_float2(acc[m][n].z, acc[m][n].w);
        }
    }
}

// ---------------------------------------------------------------------------
// Kernel 2: flash attention with relative-position skew.
//
// Srel[i,j] = q_i . Er[S-1-(i-j)]  (j<=i) | 0 (j=i+1) | q_{i+1} . Er[j-i-2] (j>=i+2)
//
// S, R1, R2: bf16 m16n8k16 single-pass.
// PV: tf32 m16n8k8 single-pass (P via smem round-trip; V staged pre-converted
// to tf32 in its natural [j][d] layout — k8 B operand needs no transpose).
// ---------------------------------------------------------------------------
#define QP 68
#define KP2 72     /* packed bf16x2 K^T rows: [32][72] */
#define VP 72
#define WP2 200    /* packed bf16x2 Er windows: [32][200] */
#define RP 84
#define SM_Q  0
#define SM_K  (129 * QP)              /* 8772  */
#define SM_V  (SM_K + 32 * KP2)       /* 11076 */
#define SM_W1 (SM_V + 64 * VP)        /* 15684 */
#define SM_W2 (SM_W1 + 32 * WP2)      /* 22084 */
#define SM_R  (SM_W2 + 32 * WP2)      /* 28484 */
#define SM_TOT_FLOATS (SM_R + 128 * RP)   /* 39236 */
#define SMEM_BYTES (SM_TOT_FLOATS * 4)

__global__ void __launch_bounds__(256, 1) attn_kernel(
    const float* __restrict__ Er, float* __restrict__ out)
{
    extern __shared__ float sm[];
    float* Qs   = sm + SM_Q;                 // [129][QP] fp32 Q rows (prologue); later P (tf32 bits)
    unsigned* Khs = (unsigned*)(sm + SM_K);  // [32][KP2] bf16x2 K^T [d2][j]
    float* Vs   = sm + SM_V;                 // [64][VP]  V [j][d] pre-converted to tf32 bits
    unsigned* W1h = (unsigned*)(sm + SM_W1); // [32][WP2] bf16x2 Er window 1
    unsigned* W2h = (unsigned*)(sm + SM_W2); // [32][WP2] bf16x2 Er window 2
    float* Rscr = sm + SM_R;                 // [128][RP] per-warp R scratch
    unsigned* Pb = (unsigned*)sm;            // P tf32 bits [128][QP] (overlays Qs)
    const unsigned* Vsu = (const unsigned*)Vs;

    const int tid  = threadIdx.x;
    const int lane = tid & 31;
    const int warp = tid >> 5;
    const int g = lane >> 2;     // 0..7
    const int t = lane & 3;      // 0..3
    const int rbase = warp * 16;

    const int bh = blockIdx.y;
    const int i0 = blockIdx.x * 128;

    const float* qb0 = g_q + (size_t)bh * SS * HD;
    const float* kb0 = g_k + (size_t)bh * SS * HD;
    const float* vb0 = g_v + (size_t)bh * SS * HD;

    // ---- stage Q rows i0..i0+128 ----
    for (int idx = tid; idx < 129 * 16; idx += 256) {
        int r = idx >> 4, dq = (idx & 15) * 4;
        float4 v = make_float4(0.f, 0.f, 0.f, 0.f);
        int gi = i0 + r;
        if (gi < SS) v = *(const float4*)&qb0[(size_t)gi * HD + dq];
        *(float4*)&Qs[r * QP + dq] = v;
    }
    __syncthreads();

    // ---- resident A fragments (bf16, 4 k16 steps) ----
    unsigned aq[4][4], aq2[4][4];
    {
        const float* r0 = &Qs[(rbase + g) * QP];
        const float* r1 = &Qs[(rbase + g + 8) * QP];
        const float* s0 = &Qs[(rbase + g + 1) * QP];
        const float* s1 = &Qs[(rbase + g + 9) * QP];
        #pragma unroll
        for (int s = 0; s < 4; s++) {
            float2 f0 = *(const float2*)&r0[16 * s + 2 * t];
            float2 f1 = *(const float2*)&r1[16 * s + 2 * t];
            float2 f2 = *(const float2*)&r0[16 * s + 2 * t + 8];
            float2 f3 = *(const float2*)&r1[16 * s + 2 * t + 8];
            aq[s][0] = pk2(f0.y, f0.x);
            aq[s][1] = pk2(f1.y, f1.x);
            aq[s][2] = pk2(f2.y, f2.x);
            aq[s][3] = pk2(f3.y, f3.x);
            float2 h0 = *(const float2*)&s0[16 * s + 2 * t];
            float2 h1 = *(const float2*)&s1[16 * s + 2 * t];
            float2 h2 = *(const float2*)&s0[16 * s + 2 * t + 8];
            float2 h3 = *(const float2*)&s1[16 * s + 2 * t + 8];
            aq2[s][0] = pk2(h0.y, h0.x);
            aq2[s][1] = pk2(h1.y, h1.x);
            aq2[s][2] = pk2(h2.y, h2.x);
            aq2[s][3] = pk2(h3.y, h3.x);
        }
    }
    __syncthreads();  // frag build done before Pb overwrites Qs

    float4 Oacc[8];
    #pragma unroll
    for (int n = 0; n < 8; n++) Oacc[n] = make_float4(0.f, 0.f, 0.f, 0.f);
    float m0r = -1e30f, m1r = -1e30f, l0r = 0.f, l1r = 0.f;

    const float* rp0 = &Rscr[(rbase + g) * RP];
    const float* rp1 = &Rscr[(rbase + g + 8) * RP];
    float* wr0 = &Rscr[(rbase + g) * RP + 2 * t];
    float* wr1 = &Rscr[(rbase + g + 8) * RP + 2 * t];
    unsigned* Pb0 = Pb + (rbase + g) * QP;
    unsigned* Pb1 = Pb + (rbase + g + 8) * QP;
    const int off1w = 112 - rbase;
    const int tlb = 2 * t + 15 - g;
    const int diffb = (2 * t) - (i0 + rbase + g);

    for (int j0 = 0; j0 < SS; j0 += 64) {
        __syncthreads();  // previous tile compute (incl PV reads of Vs/Pb) done

        const bool need1 = (j0 <= i0 + 127);
        const bool need2 = (j0 + 63 >= i0 + 2);
        const int L1 = SS - 128 - i0 + j0;
        const int L2 = j0 - i0 - 129;

        // ---- stage K^T packed bf16x2 [d2][j]; V [j][d] pre-converted tf32 ----
        for (int idx = tid; idx < 64 * 16; idx += 256) {
            int j = idx >> 4, dq = (idx & 15) * 4;
            float4 kv = *(const float4*)&kb0[(size_t)(j0 + j) * HD + dq];
            int d2 = dq >> 1;
            Khs[d2 * KP2 + j]       = pk2(kv.y, kv.x);
            Khs[(d2 + 1) * KP2 + j] = pk2(kv.w, kv.z);
            float4 vv = *(const float4*)&vb0[(size_t)(j0 + j) * HD + dq];
            float4 cv;
            cv.x = __uint_as_float(f2tf(vv.x));
            cv.y = __uint_as_float(f2tf(vv.y));
            cv.z = __uint_as_float(f2tf(vv.z));
            cv.w = __uint_as_float(f2tf(vv.w));
            *(float4*)&Vs[j * VP + dq] = cv;
        }
        if (need1) {
            for (int idx = tid; idx < 192 * 16; idx += 256) {
                int tl = idx >> 4, dq = (idx & 15) * 4;
                int l = L1 + tl;
                float4 e = make_float4(0.f, 0.f, 0.f, 0.f);
                if (l >= 0 && l < SS) e = *(const float4*)&Er[(size_t)l * HD + dq];
                int d2 = dq >> 1;
                W1h[d2 * WP2 + tl]       = pk2(e.y, e.x);
                W1h[(d2 + 1) * WP2 + tl] = pk2(e.w, e.z);
            }
        }
        if (need2) {
            for (int idx = tid; idx < 192 * 16; idx += 256) {
                int tl = idx >> 4, dq = (idx & 15) * 4;
                int l = L2 + tl;
                float4 e = make_float4(0.f, 0.f, 0.f, 0.f);
                if (l >= 0 && l < SS) e = *(const float4*)&Er[(size_t)l * HD + dq];
                int d2 = dq >> 1;
                W2h[d2 * WP2 + tl]       = pk2(e.y, e.x);
                W2h[(d2 + 1) * WP2 + tl] = pk2(e.w, e.z);
            }
        }
        __syncthreads();

        // ---- S = Q K^T (bf16, 32 mma) ----
        float4 sacc[8];
        #pragma unroll
        for (int n = 0; n < 8; n++) {
            float4 c = make_float4(0.f, 0.f, 0.f, 0.f);
            #pragma unroll
            for (int s = 0; s < 4; s++) {
                unsigned b0 = Khs[(8 * s + t) * KP2 + 8 * n + g];
                unsigned b1 = Khs[(8 * s + t + 4) * KP2 + 8 * n + g];
                mma16(c, aq[s][0], aq[s][1], aq[s][2], aq[s][3], b0, b1);
            }
            sacc[n] = c;
        }

        const bool wneed1 = (j0 <= i0 + rbase + 15);
        const bool wneed2 = (j0 + 63 >= i0 + rbase + 2);

        // ---- case-1 relative term (bf16, 40 mma) ----
        if (wneed1) {
            #pragma unroll
            for (int n = 0; n < 10; n++) {
                float4 c = make_float4(0.f, 0.f, 0.f, 0.f);
                #pragma unroll
                for (int s = 0; s < 4; s++) {
                    unsigned b0 = W1h[(8 * s + t) * WP2 + off1w + 8 * n + g];
                    unsigned b1 = W1h[(8 * s + t + 4) * WP2 + off1w + 8 * n + g];
                    mma16(c, aq[s][0], aq[s][1], aq[s][2], aq[s][3], b0, b1);
                }
                wr0[8 * n] = c.x; wr0[8 * n + 1] = c.y;
                wr1[8 * n] = c.z; wr1[8 * n + 1] = c.w;
            }
            __syncwarp();
            #pragma unroll
            for (int n = 0; n < 8; n++) {
                int d00 = diffb + j0 + 8 * n;
                int tl = tlb + 8 * n;
                if (d00 <= 0)     sacc[n].x += rp0[tl];
                if (d00 + 1 <= 0) sacc[n].y += rp0[tl + 1];
                if (d00 - 8 <= 0) sacc[n].z += rp1[tl - 8];
                if (d00 - 7 <= 0) sacc[n].w += rp1[tl - 7];
            }
            __syncwarp();
        }
        // ---- case-2 relative term (bf16, 40 mma) ----
        if (wneed2) {
            #pragma unroll
            for (int n = 0; n < 10; n++) {
                float4 c = make_float4(0.f, 0.f, 0.f, 0.f);
                #pragma unroll
                for (int s = 0; s < 4; s++) {
                    unsigned b0 = W2h[(8 * s + t) * WP2 + off1w + 8 * n + g];
                    unsigned b1 = W2h[(8 * s + t + 4) * WP2 + off1w + 8 * n + g];
                    mma16(c, aq2[s][0], aq2[s][1], aq2[s][2], aq2[s][3], b0, b1);
                }
                wr0[8 * n] = c.x; wr0[8 * n + 1] = c.y;
                wr1[8 * n] = c.z; wr1[8 * n + 1] = c.w;
            }
            __syncwarp();
            #pragma unroll
            for (int n = 0; n < 8; n++) {
                int d00 = diffb + j0 + 8 * n;
                int tl = tlb + 8 * n;
                if (d00 >= 2)     sacc[n].x += rp0[tl];
                if (d00 + 1 >= 2) sacc[n].y += rp0[tl + 1];
                if (d00 - 8 >= 2) sacc[n].z += rp1[tl - 8];
                if (d00 - 7 >= 2) sacc[n].w += rp1[tl - 7];
            }
            __syncwarp();
        }

        // ---- scale + online softmax ----
        float mx0 = -1e30f, mx1 = -1e30f;
        #pragma unroll
        for (int n = 0; n < 8; n++) {
            sacc[n].x *= SCALE; sacc[n].y *= SCALE;
            sacc[n].z *= SCALE; sacc[n].w *= SCALE;
            mx0 = fmaxf(mx0, fmaxf(sacc[n].x, sacc[n].y));
            mx1 = fmaxf(mx1, fmaxf(sacc[n].z, sacc[n].w));
        }
        #pragma unroll
        for (int off = 1; off <= 2; off <<= 1) {
            mx0 = fmaxf(mx0, __shfl_xor_sync(0xffffffffu, mx0, off));
            mx1 = fmaxf(mx1, __shfl_xor_sync(0xffffffffu, mx1, off));
        }
        float mn0 = fmaxf(m0r, mx0), mn1 = fmaxf(m1r, mx1);
        float c0 = __expf(m0r - mn0), c1 = __expf(m1r - mn1);
        float rs0 = 0.f, rs1 = 0.f;
        #pragma unroll
        for (int n = 0; n < 8; n++) {
            sacc[n].x = __expf(sacc[n].x - mn0);
            sacc[n].y = __expf(sacc[n].y - mn0);
            sacc[n].z = __expf(sacc[n].z - mn1);
            sacc[n].w = __expf(sacc[n].w - mn1);
            rs0 += sacc[n].x + sacc[n].y;
            rs1 += sacc[n].z + sacc[n].w;
        }
        #pragma unroll
        for (int off = 1; off <= 2; off <<= 1) {
            rs0 += __shfl_xor_sync(0xffffffffu, rs0, off);
            rs1 += __shfl_xor_sync(0xffffffffu, rs1, off);
        }
        l0r = l0r * c0 + rs0;  m0r = mn0;
        l1r = l1r * c1 + rs1;  m1r = mn1;
        #pragma unroll
        for (int n = 0; n < 8; n++) {
            Oacc[n].x *= c0; Oacc[n].y *= c0;
            Oacc[n].z *= c1; Oacc[n].w *= c1;
        }

        // ---- stage P (tf32 bits, warp-private rows) ----
        #pragma unroll
        for (int n = 0; n < 8; n++) {
            Pb0[8 * n + 2 * t]     = f2tf(sacc[n].x);
            Pb0[8 * n + 2 * t + 1] = f2tf(sacc[n].y);
            Pb1[8 * n + 2 * t]     = f2tf(sacc[n].z);
            Pb1[8 * n + 2 * t + 1] = f2tf(sacc[n].w);
        }
        __syncwarp();

        // ---- O += P V  (tf32 single-pass, 64 mma; B = V[j][d] as staged) ----
        #pragma unroll
        for (int sp = 0; sp < 8; sp++) {
            unsigned a0 = Pb0[8 * sp + t];
            unsigned a1 = Pb1[8 * sp + t];
            unsigned a2 = Pb0[8 * sp + t + 4];
            unsigned a3 = Pb1[8 * sp + t + 4];
            #pragma unroll
            for (int n = 0; n < 8; n++) {
                unsigned b0 = Vsu[(8 * sp + t) * VP + 8 * n + g];
                unsigned b1 = Vsu[(8 * sp + t + 4) * VP + 8 * n + g];
                mma8(Oacc[n], a0, a1, a2, a3, b0, b1);
            }
        }
        __syncwarp();
    }

    // ---- normalize + write out [b][s][h*64+d] ----
    const int b_ = bh >> 3, h = bh & 7;
    const float inv0 = 1.0f / l0r, inv1 = 1.0f / l1r;
    float* op0 = out + ((size_t)b_ * SS + (i0 + rbase + g)) * EE + h * HD;
    float* op1 = out + ((size_t)b_ * SS + (i0 + rbase + g + 8)) * EE + h * HD;
    #pragma unroll
    for (int n = 0; n < 8; n++) {
        *(float2*)&op0[8 * n + 2 * t] = make_float2(Oacc[n].x * inv0, Oacc[n].y * inv0);
        *(float2*)&op1[8 * n + 2 * t] = make_float2(Oacc[n].z * inv1, Oacc[n].w * inv1);
    }
}

// ---------------------------------------------------------------------------
// Kernel 3: in-place LayerNorm over E=512 per (b,s) row.
// ---------------------------------------------------------------------------
__global__ void __launch_bounds__(256) ln_kernel(
    float* __restrict__ out,
    const float* __restrict__ gamma,
    const float* __restrict__ beta)
{
    __shared__ float red[16];
    const int row = blockIdx.x;
    float* p = out + (size_t)row * EE;
    const int tid = threadIdx.x;

    float v0 = p[tid], v1 = p[tid + 256];
    float s = v0 + v1;
    float q = v0 * v0 + v1 * v1;
    #pragma unroll
    for (int off = 16; off > 0; off >>= 1) {
        s += __shfl_xor_sync(0xffffffffu, s, off);
        q += __shfl_xor_sync(0xffffffffu, q, off);
    }
    const int wid = tid >> 5, lid = tid & 31;
    if (lid == 0) { red[wid] = s; red[8 + wid] = q; }
    __syncthreads();
    s = 0.0f; q = 0.0f;
    #pragma unroll
    for (int w = 0; w < 8; w++) { s += red[w]; q += red[8 + w]; }

    float mu = s * (1.0f / EE);
    float var = q * (1.0f / EE) - mu * mu;
    float inv = rsqrtf(var + 1e-5f);
    p[tid]       = (v0 - mu) * inv * gamma[tid]       + beta[tid];
    p[tid + 256] = (v1 - mu) * inv * gamma[tid + 256] + beta[tid + 256];
}

// ---------------------------------------------------------------------------
extern "C" void kernel_launch(void* const* d_in, const int* in_sizes, int n_in,
                              void* d_out, int out_size)
{
    const float* x     = (const float*)d_in[0];
    const float* Wq    = (const float*)d_in[1];
    const float* Wk    = (const float*)d_in[2];
    const float* Wv    = (const float*)d_in[3];
    const float* Er    = (const float*)d_in[4];
    const float* gamma = (const float*)d_in[5];
    const float* beta  = (const float*)d_in[6];
    float* out = (float*)d_out;

    cudaFuncSetAttribute(qkv_mma_kernel,
                         cudaFuncAttributeMaxDynamicSharedMemorySize, QKV_SMEM_BYTES);
    cudaFuncSetAttribute(attn_kernel,
                         cudaFuncAttributeMaxDynamicSharedMemorySize, SMEM_BYTES);

    qkv_mma_kernel<<<dim3(EE / 128, (BB * SS) / 128, 3), 256, QKV_SMEM_BYTES>>>(x, Wq, Wk, Wv);
    attn_kernel<<<dim3(SS / 128, BB * HH), 256, SMEM_BYTES>>>(Er, out);
    ln_kernel<<<BB * SS, 256>>>(out, gamma, beta);
}

// round 9
// speedup vs baseline: 1.5673x; 1.0184x over previous
#include <cuda_runtime.h>
#include <math.h>

#define BB 4
#define SS 2048
#define EE 512
#define HH 8
#define HD 64
#define SCALE 0.04419417382415922f  /* 512^-0.5 (reference scales by E, not HD) */

// Scratch (static device arrays — allocation rules forbid cudaMalloc)
__device__ float g_q[BB * HH * SS * HD];
__device__ float g_k[BB * HH * SS * HD];
__device__ float g_v[BB * HH * SS * HD];

// ---------------------------------------------------------------------------
// helpers
// ---------------------------------------------------------------------------
__device__ __forceinline__ unsigned f2tf(float x) {
    unsigned r; asm("cvt.rna.tf32.f32 %0, %1;" : "=r"(r) : "f"(x)); return r;
}
__device__ __forceinline__ unsigned pk2(float hi, float lo) {
    unsigned r; asm("cvt.rn.bf16x2.f32 %0, %1, %2;" : "=r"(r) : "f"(hi), "f"(lo)); return r;
}
__device__ __forceinline__ float lo16f(unsigned u) { return __uint_as_float(u << 16); }
__device__ __forceinline__ float hi16f(unsigned u) { return __uint_as_float(u & 0xffff0000u); }

__device__ __forceinline__ void mma8(float4& c,
    unsigned a0, unsigned a1, unsigned a2, unsigned a3, unsigned b0, unsigned b1)
{
    asm("mma.sync.aligned.m16n8k8.row.col.f32.tf32.tf32.f32 "
        "{%0,%1,%2,%3}, {%4,%5,%6,%7}, {%8,%9}, {%0,%1,%2,%3};"
        : "+f"(c.x), "+f"(c.y), "+f"(c.z), "+f"(c.w)
        : "r"(a0), "r"(a1), "r"(a2), "r"(a3), "r"(b0), "r"(b1));
}
__device__ __forceinline__ void mma16(float4& c,
    unsigned a0, unsigned a1, unsigned a2, unsigned a3, unsigned b0, unsigned b1)
{
    asm("mma.sync.aligned.m16n8k16.row.col.f32.bf16.bf16.f32 "
        "{%0,%1,%2,%3}, {%4,%5,%6,%7}, {%8,%9}, {%0,%1,%2,%3};"
        : "+f"(c.x), "+f"(c.y), "+f"(c.z), "+f"(c.w)
        : "r"(a0), "r"(a1), "r"(a2), "r"(a3), "r"(b0), "r"(b1));
}
__device__ __forceinline__ void cpa16(float* dst, const float* src) {
    unsigned sa = (unsigned)__cvta_generic_to_shared(dst);
    asm volatile("cp.async.cg.shared.global [%0], [%1], 16;" :: "r"(sa), "l"(src));
}
#define CP_COMMIT() asm volatile("cp.async.commit_group;")
#define CP_WAIT(n)  asm volatile("cp.async.wait_group %0;" :: "n"(n))

// ---------------------------------------------------------------------------
// Kernel 1a: Q/K projection, tf32 single-pass, occupancy 2.
// ---------------------------------------------------------------------------
#define QKV_SMEM_BYTES (18432 * 4)

__global__ void __launch_bounds__(256, 2) qk_kernel(
    const float* __restrict__ x, const float* __restrict__ Wq,
    const float* __restrict__ Wk)
{
    extern __shared__ float sm[];
    const int z = blockIdx.z;
    const float* W = z == 0 ? Wq : Wk;
    float* outp = z == 0 ? g_q : g_k;
    const int m0 = blockIdx.y * 128, n0 = blockIdx.x * 128;
    const int tid = threadIdx.x, lane = tid & 31, warp = tid >> 5;
    const int g = lane >> 2, t = lane & 3;
    const int mw = (warp >> 2) * 64, nw = (warp & 3) * 32;

    float* Xs[2] = { sm, sm + 4608 };
    float* Ws[2] = { sm + 9216, sm + 13824 };
    const int r_ = tid >> 1, c_ = (tid & 1) * 16;
    #define STAGE(buf, k0) do { \
        cpa16(Xs[buf] + r_ * 36 + c_,      &x[(size_t)(m0 + r_) * EE + (k0) + c_]); \
        cpa16(Xs[buf] + r_ * 36 + c_ + 4,  &x[(size_t)(m0 + r_) * EE + (k0) + c_ + 4]); \
        cpa16(Xs[buf] + r_ * 36 + c_ + 8,  &x[(size_t)(m0 + r_) * EE + (k0) + c_ + 8]); \
        cpa16(Xs[buf] + r_ * 36 + c_ + 12, &x[(size_t)(m0 + r_) * EE + (k0) + c_ + 12]); \
        cpa16(Ws[buf] + r_ * 36 + c_,      &W[(size_t)(n0 + r_) * EE + (k0) + c_]); \
        cpa16(Ws[buf] + r_ * 36 + c_ + 4,  &W[(size_t)(n0 + r_) * EE + (k0) + c_ + 4]); \
        cpa16(Ws[buf] + r_ * 36 + c_ + 8,  &W[(size_t)(n0 + r_) * EE + (k0) + c_ + 8]); \
        cpa16(Ws[buf] + r_ * 36 + c_ + 12, &W[(size_t)(n0 + r_) * EE + (k0) + c_ + 12]); \
        CP_COMMIT(); \
    } while (0)

    float4 acc[4][4];
    #pragma unroll
    for (int m = 0; m < 4; m++)
        #pragma unroll
        for (int n = 0; n < 4; n++) acc[m][n] = make_float4(0.f, 0.f, 0.f, 0.f);

    STAGE(0, 0);
    for (int p = 0; p < 16; p++) {
        if (p < 15) STAGE((p + 1) & 1, (p + 1) * 32);
        if (p < 15) { CP_WAIT(1); } else { CP_WAIT(0); }
        __syncthreads();
        const float* Xb = Xs[p & 1];
        const float* Wb = Ws[p & 1];
        #pragma unroll
        for (int s = 0; s < 4; s++) {
            unsigned a[4][4], b[4][2];
            #pragma unroll
            for (int m = 0; m < 4; m++) {
                const float* r0 = &Xb[(mw + 16 * m + g) * 36 + 8 * s];
                const float* r1 = &Xb[(mw + 16 * m + g + 8) * 36 + 8 * s];
                a[m][0] = f2tf(r0[t]); a[m][1] = f2tf(r1[t]);
                a[m][2] = f2tf(r0[t + 4]); a[m][3] = f2tf(r1[t + 4]);
            }
            #pragma unroll
            for (int n = 0; n < 4; n++) {
                const float* w0 = &Wb[(nw + 8 * n + g) * 36 + 8 * s];
                b[n][0] = f2tf(w0[t]); b[n][1] = f2tf(w0[t + 4]);
            }
            #pragma unroll
            for (int m = 0; m < 4; m++)
                #pragma unroll
                for (int n = 0; n < 4; n++)
                    mma8(acc[m][n], a[m][0], a[m][1], a[m][2], a[m][3], b[n][0], b[n][1]);
        }
        __syncthreads();
    }

    #pragma unroll
    for (int m = 0; m < 4; m++) {
        int r0 = m0 + mw + 16 * m + g, r1 = r0 + 8;
        int b0_ = r0 >> 11, s0_ = r0 & 2047;
        int b1_ = r1 >> 11, s1_ = r1 & 2047;
        #pragma unroll
        for (int n = 0; n < 4; n++) {
            int col = n0 + nw + 8 * n + 2 * t;
            int h = col >> 6, d = col & 63;
            *(float2*)&outp[(((size_t)b0_ * HH + h) * SS + s0_) * HD + d] = make_float2(acc[m][n].x, acc[m][n].y);
            *(float2*)&outp[(((size_t)b1_ * HH + h) * SS + s1_) * HD + d] = make_float2(acc[m][n].z, acc[m][n].w);
        }
    }
}

// ---------------------------------------------------------------------------
// Kernel 1b: V projection, bf16 3-pass split (near-fp32), occupancy 1.
// ---------------------------------------------------------------------------
__global__ void __launch_bounds__(256, 1) v_kernel(
    const float* __restrict__ x, const float* __restrict__ Wv)
{
    extern __shared__ float sm[];
    const float* W = Wv;
    float* outp = g_v;
    const int m0 = blockIdx.y * 128, n0 = blockIdx.x * 128;
    const int tid = threadIdx.x, lane = tid & 31, warp = tid >> 5;
    const int g = lane >> 2, t = lane & 3;
    const int mw = (warp >> 2) * 64, nw = (warp & 3) * 32;

    float* Xs[2] = { sm, sm + 4608 };
    float* Ws[2] = { sm + 9216, sm + 13824 };
    const int r_ = tid >> 1, c_ = (tid & 1) * 16;

    float4 acc[4][4];
    #pragma unroll
    for (int m = 0; m < 4; m++)
        #pragma unroll
        for (int n = 0; n < 4; n++) acc[m][n] = make_float4(0.f, 0.f, 0.f, 0.f);

    STAGE(0, 0);
    for (int p = 0; p < 16; p++) {
        if (p < 15) STAGE((p + 1) & 1, (p + 1) * 32);
        if (p < 15) { CP_WAIT(1); } else { CP_WAIT(0); }
        __syncthreads();
        const float* Xb = Xs[p & 1];
        const float* Wb = Ws[p & 1];
        #pragma unroll
        for (int s = 0; s < 2; s++) {
            unsigned ah[4][4], al[4][4], bh[4][2], bl[4][2];
            #pragma unroll
            for (int m = 0; m < 4; m++) {
                const float* r0 = &Xb[(mw + 16 * m + g) * 36 + 16 * s];
                const float* r1 = &Xb[(mw + 16 * m + g + 8) * 36 + 16 * s];
                float2 f0 = *(const float2*)&r0[2 * t];
                float2 f1 = *(const float2*)&r1[2 * t];
                float2 f2 = *(const float2*)&r0[2 * t + 8];
                float2 f3 = *(const float2*)&r1[2 * t + 8];
                ah[m][0] = pk2(f0.y, f0.x); al[m][0] = pk2(f0.y - hi16f(ah[m][0]), f0.x - lo16f(ah[m][0]));
                ah[m][1] = pk2(f1.y, f1.x); al[m][1] = pk2(f1.y - hi16f(ah[m][1]), f1.x - lo16f(ah[m][1]));
                ah[m][2] = pk2(f2.y, f2.x); al[m][2] = pk2(f2.y - hi16f(ah[m][2]), f2.x - lo16f(ah[m][2]));
                ah[m][3] = pk2(f3.y, f3.x); al[m][3] = pk2(f3.y - hi16f(ah[m][3]), f3.x - lo16f(ah[m][3]));
            }
            #pragma unroll
            for (int n = 0; n < 4; n++) {
                const float* w0 = &Wb[(nw + 8 * n + g) * 36 + 16 * s];
                float2 f0 = *(const float2*)&w0[2 * t];
                float2 f1 = *(const float2*)&w0[2 * t + 8];
                bh[n][0] = pk2(f0.y, f0.x); bl[n][0] = pk2(f0.y - hi16f(bh[n][0]), f0.x - lo16f(bh[n][0]));
                bh[n][1] = pk2(f1.y, f1.x); bl[n][1] = pk2(f1.y - hi16f(bh[n][1]), f1.x - lo16f(bh[n][1]));
            }
            #pragma unroll
            for (int m = 0; m < 4; m++)
                #pragma unroll
                for (int n = 0; n < 4; n++) {
                    mma16(acc[m][n], ah[m][0], ah[m][1], ah[m][2], ah[m][3], bh[n][0], bh[n][1]);
                    mma16(acc[m][n], ah[m][0], ah[m][1], ah[m][2], ah[m][3], bl[n][0], bl[n][1]);
                    mma16(acc[m][n], al[m][0], al[m][1], al[m][2], al[m][3], bh[n][0], bh[n][1]);
                }
        }
        __syncthreads();
    }

    #pragma unroll
    for (int m = 0; m < 4; m++) {
        int r0 = m0 + mw + 16 * m + g, r1 = r0 + 8;
        int b0_ = r0 >> 11, s0_ = r0 & 2047;
        int b1_ = r1 >> 11, s1_ = r1 & 2047;
        #pragma unroll
        for (int n = 0; n < 4; n++) {
            int col = n0 + nw + 8 * n + 2 * t;
            int h = col >> 6, d = col & 63;
            *(float2*)&outp[(((size_t)b0_ * HH + h) * SS + s0_) * HD + d] = make_float2(acc[m][n].x, acc[m][n].y);
            *(float2*)&outp[(((size_t)b1_ * HH + h) * SS + s1_) * HD + d] = make_float2(acc[m][n].z, acc[m][n].w);
        }
    }
}

// ---------------------------------------------------------------------------
// Kernel 2: flash attention with relative-position skew — 64-row CTAs,
// 128 threads, 2 CTAs/SM (phase overlap across co-resident CTAs).
//
// Srel[i,j] = q_i . Er[S-1-(i-j)]  (j<=i) | 0 (j=i+1) | q_{i+1} . Er[j-i-2] (j>=i+2)
//
// S, R1, R2: bf16 m16n8k16 single-pass.  PV: tf32 m16n8k8 single-pass.
// ---------------------------------------------------------------------------
#define QP 68
#define KP2 72
#define VP 72
#define WP2 136    /* 128-wide Er windows (64-row block) + pad */
#define RP 84
#define SM_Q  0                       /* 65 x QP = 4420 */
#define SM_K  4420                    /* 32 x KP2 = 2304 */
#define SM_V  6724                    /* 64 x VP = 4608 */
#define SM_W1 11332                   /* 32 x WP2 = 4352 */
#define SM_W2 15684                   /* 32 x WP2 = 4352 */
#define SM_R  20036                   /* 64 x RP = 5376 */
#define SM_TOT_FLOATS 25412
#define SMEM_BYTES (SM_TOT_FLOATS * 4)   /* 101648 B -> 2 CTAs/SM */

__global__ void __launch_bounds__(128, 2) attn_kernel(
    const float* __restrict__ Er, float* __restrict__ out)
{
    extern __shared__ float sm[];
    float* Qs   = sm + SM_Q;                 // [65][QP] fp32 Q rows (prologue); later P (tf32 bits)
    unsigned* Khs = (unsigned*)(sm + SM_K);  // [32][KP2] bf16x2 K^T [d2][j]
    float* Vs   = sm + SM_V;                 // [64][VP]  V [j][d] pre-converted to tf32 bits
    unsigned* W1h = (unsigned*)(sm + SM_W1); // [32][WP2] bf16x2 Er window 1
    unsigned* W2h = (unsigned*)(sm + SM_W2); // [32][WP2] bf16x2 Er window 2
    float* Rscr = sm + SM_R;                 // [64][RP] per-warp R scratch
    unsigned* Pb = (unsigned*)sm;            // P tf32 bits [64][QP] (overlays Qs)
    const unsigned* Vsu = (const unsigned*)Vs;

    const int tid  = threadIdx.x;
    const int lane = tid & 31;
    const int warp = tid >> 5;               // 0..3
    const int g = lane >> 2;
    const int t = lane & 3;
    const int rbase = warp * 16;

    const int bh = blockIdx.y;
    const int i0 = blockIdx.x * 64;

    const float* qb0 = g_q + (size_t)bh * SS * HD;
    const float* kb0 = g_k + (size_t)bh * SS * HD;
    const float* vb0 = g_v + (size_t)bh * SS * HD;

    // ---- stage Q rows i0..i0+64 (row 64 zero-padded past S) ----
    for (int idx = tid; idx < 65 * 16; idx += 128) {
        int r = idx >> 4, dq = (idx & 15) * 4;
        float4 v = make_float4(0.f, 0.f, 0.f, 0.f);
        int gi = i0 + r;
        if (gi < SS) v = *(const float4*)&qb0[(size_t)gi * HD + dq];
        *(float4*)&Qs[r * QP + dq] = v;
    }
    __syncthreads();

    // ---- resident A fragments (bf16, 4 k16 steps) ----
    unsigned aq[4][4], aq2[4][4];
    {
        const float* r0 = &Qs[(rbase + g) * QP];
        const float* r1 = &Qs[(rbase + g + 8) * QP];
        const float* s0 = &Qs[(rbase + g + 1) * QP];
        const float* s1 = &Qs[(rbase + g + 9) * QP];
        #pragma unroll
        for (int s = 0; s < 4; s++) {
            float2 f0 = *(const float2*)&r0[16 * s + 2 * t];
            float2 f1 = *(const float2*)&r1[16 * s + 2 * t];
            float2 f2 = *(const float2*)&r0[16 * s + 2 * t + 8];
            float2 f3 = *(const float2*)&r1[16 * s + 2 * t + 8];
            aq[s][0] = pk2(f0.y, f0.x);
            aq[s][1] = pk2(f1.y, f1.x);
            aq[s][2] = pk2(f2.y, f2.x);
            aq[s][3] = pk2(f3.y, f3.x);
            float2 h0 = *(const float2*)&s0[16 * s + 2 * t];
            float2 h1 = *(const float2*)&s1[16 * s + 2 * t];
            float2 h2 = *(const float2*)&s0[16 * s + 2 * t + 8];
            float2 h3 = *(const float2*)&s1[16 * s + 2 * t + 8];
            aq2[s][0] = pk2(h0.y, h0.x);
            aq2[s][1] = pk2(h1.y, h1.x);
            aq2[s][2] = pk2(h2.y, h2.x);
            aq2[s][3] = pk2(h3.y, h3.x);
        }
    }
    __syncthreads();  // frag build done before Pb overwrites Qs

    float4 Oacc[8];
    #pragma unroll
    for (int n = 0; n < 8; n++) Oacc[n] = make_float4(0.f, 0.f, 0.f, 0.f);
    float m0r = -1e30f, m1r = -1e30f, l0r = 0.f, l1r = 0.f;

    const float* rp0 = &Rscr[(rbase + g) * RP];
    const float* rp1 = &Rscr[(rbase + g + 8) * RP];
    float* wr0 = &Rscr[(rbase + g) * RP + 2 * t];
    float* wr1 = &Rscr[(rbase + g + 8) * RP + 2 * t];
    unsigned* Pb0 = Pb + (rbase + g) * QP;
    unsigned* Pb1 = Pb + (rbase + g + 8) * QP;
    const int off1w = 48 - rbase;
    const int tlb = 2 * t + 15 - g;
    const int diffb = (2 * t) - (i0 + rbase + g);

    for (int j0 = 0; j0 < SS; j0 += 64) {
        __syncthreads();  // previous tile compute (PV reads of Vs/Pb) done

        const bool need1 = (j0 <= i0 + 63);
        const bool need2 = (j0 + 63 >= i0 + 2);
        const int L1 = SS - 64 - i0 + j0;
        const int L2 = j0 - i0 - 65;

        // ---- stage K^T packed bf16x2 [d2][j]; V [j][d] pre-converted tf32 ----
        for (int idx = tid; idx < 64 * 16; idx += 128) {
            int j = idx >> 4, dq = (idx & 15) * 4;
            float4 kv = *(const float4*)&kb0[(size_t)(j0 + j) * HD + dq];
            int d2 = dq >> 1;
            Khs[d2 * KP2 + j]       = pk2(kv.y, kv.x);
            Khs[(d2 + 1) * KP2 + j] = pk2(kv.w, kv.z);
            float4 vv = *(const float4*)&vb0[(size_t)(j0 + j) * HD + dq];
            float4 cv;
            cv.x = __uint_as_float(f2tf(vv.x));
            cv.y = __uint_as_float(f2tf(vv.y));
            cv.z = __uint_as_float(f2tf(vv.z));
            cv.w = __uint_as_float(f2tf(vv.w));
            *(float4*)&Vs[j * VP + dq] = cv;
        }
        if (need1) {
            for (int idx = tid; idx < 128 * 16; idx += 128) {
                int tl = idx >> 4, dq = (idx & 15) * 4;
                int l = L1 + tl;
                float4 e = make_float4(0.f, 0.f, 0.f, 0.f);
                if (l >= 0 && l < SS) e = *(const float4*)&Er[(size_t)l * HD + dq];
                int d2 = dq >> 1;
                W1h[d2 * WP2 + tl]       = pk2(e.y, e.x);
                W1h[(d2 + 1) * WP2 + tl] = pk2(e.w, e.z);
            }
        }
        if (need2) {
            for (int idx = tid; idx < 128 * 16; idx += 128) {
                int tl = idx >> 4, dq = (idx & 15) * 4;
                int l = L2 + tl;
                float4 e = make_float4(0.f, 0.f, 0.f, 0.f);
                if (l >= 0 && l < SS) e = *(const float4*)&Er[(size_t)l * HD + dq];
                int d2 = dq >> 1;
                W2h[d2 * WP2 + tl]       = pk2(e.y, e.x);
                W2h[(d2 + 1) * WP2 + tl] = pk2(e.w, e.z);
            }
        }
        __syncthreads();

        // ---- S = Q K^T (bf16, 32 mma) ----
        float4 sacc[8];
        #pragma unroll
        for (int n = 0; n < 8; n++) {
            float4 c = make_float4(0.f, 0.f, 0.f, 0.f);
            #pragma unroll
            for (int s = 0; s < 4; s++) {
                unsigned b0 = Khs[(8 * s + t) * KP2 + 8 * n + g];
                unsigned b1 = Khs[(8 * s + t + 4) * KP2 + 8 * n + g];
                mma16(c, aq[s][0], aq[s][1], aq[s][2], aq[s][3], b0, b1);
            }
            sacc[n] = c;
        }

        const bool wneed1 = (j0 <= i0 + rbase + 15);
        const bool wneed2 = (j0 + 63 >= i0 + rbase + 2);

        // ---- case-1 relative term (bf16, 40 mma) ----
        if (wneed1) {
            #pragma unroll
            for (int n = 0; n < 10; n++) {
                float4 c = make_float4(0.f, 0.f, 0.f, 0.f);
                #pragma unroll
                for (int s = 0; s < 4; s++) {
                    unsigned b0 = W1h[(8 * s + t) * WP2 + off1w + 8 * n + g];
                    unsigned b1 = W1h[(8 * s + t + 4) * WP2 + off1w + 8 * n + g];
                    mma16(c, aq[s][0], aq[s][1], aq[s][2], aq[s][3], b0, b1);
                }
                wr0[8 * n] = c.x; wr0[8 * n + 1] = c.y;
                wr1[8 * n] = c.z; wr1[8 * n + 1] = c.w;
            }
            __syncwarp();
            #pragma unroll
            for (int n = 0; n < 8; n++) {
                int d00 = diffb + j0 + 8 * n;
                int tl = tlb + 8 * n;
                if (d00 <= 0)     sacc[n].x += rp0[tl];
                if (d00 + 1 <= 0) sacc[n].y += rp0[tl + 1];
                if (d00 - 8 <= 0) sacc[n].z += rp1[tl - 8];
                if (d00 - 7 <= 0) sacc[n].w += rp1[tl - 7];
            }
            __syncwarp();
        }
        // ---- case-2 relative term (bf16, 40 mma) ----
        if (wneed2) {
            #pragma unroll
            for (int n = 0; n < 10; n++) {
                float4 c = make_float4(0.f, 0.f, 0.f, 0.f);
                #pragma unroll
                for (int s = 0; s < 4; s++) {
                    unsigned b0 = W2h[(8 * s + t) * WP2 + off1w + 8 * n + g];
                    unsigned b1 = W2h[(8 * s + t + 4) * WP2 + off1w + 8 * n + g];
                    mma16(c, aq2[s][0], aq2[s][1], aq2[s][2], aq2[s][3], b0, b1);
                }
                wr0[8 * n] = c.x; wr0[8 * n + 1] = c.y;
                wr1[8 * n] = c.z; wr1[8 * n + 1] = c.w;
            }
            __syncwarp();
            #pragma unroll
            for (int n = 0; n < 8; n++) {
                int d00 = diffb + j0 + 8 * n;
                int tl = tlb + 8 * n;
                if (d00 >= 2)     sacc[n].x += rp0[tl];
                if (d00 + 1 >= 2) sacc[n].y += rp0[tl + 1];
                if (d00 - 8 >= 2) sacc[n].z += rp1[tl - 8];
                if (d00 - 7 >= 2) sacc[n].w += rp1[tl - 7];
            }
            __syncwarp();
        }

        // ---- scale + online softmax ----
        float mx0 = -1e30f, mx1 = -1e30f;
        #pragma unroll
        for (int n = 0; n < 8; n++) {
            sacc[n].x *= SCALE; sacc[n].y *= SCALE;
            sacc[n].z *= SCALE; sacc[n].w *= SCALE;
            mx0 = fmaxf(mx0, fmaxf(sacc[n].x, sacc[n].y));
            mx1 = fmaxf(mx1, fmaxf(sacc[n].z, sacc[n].w));
        }
        #pragma unroll
        for (int off = 1; off <= 2; off <<= 1) {
            mx0 = fmaxf(mx0, __shfl_xor_sync(0xffffffffu, mx0, off));
            mx1 = fmaxf(mx1, __shfl_xor_sync(0xffffffffu, mx1, off));
        }
        float mn0 = fmaxf(m0r, mx0), mn1 = fmaxf(m1r, mx1);
        float c0 = __expf(m0r - mn0), c1 = __expf(m1r - mn1);
        float rs0 = 0.f, rs1 = 0.f;
        #pragma unroll
        for (int n = 0; n < 8; n++) {
            sacc[n].x = __expf(sacc[n].x - mn0);
            sacc[n].y = __expf(sacc[n].y - mn0);
            sacc[n].z = __expf(sacc[n].z - mn1);
            sacc[n].w = __expf(sacc[n].w - mn1);
            rs0 += sacc[n].x + sacc[n].y;
            rs1 += sacc[n].z + sacc[n].w;
        }
        #pragma unroll
        for (int off = 1; off <= 2; off <<= 1) {
            rs0 += __shfl_xor_sync(0xffffffffu, rs0, off);
            rs1 += __shfl_xor_sync(0xffffffffu, rs1, off);
        }
        l0r = l0r * c0 + rs0;  m0r = mn0;
        l1r = l1r * c1 + rs1;  m1r = mn1;
        #pragma unroll
        for (int n = 0; n < 8; n++) {
            Oacc[n].x *= c0; Oacc[n].y *= c0;
            Oacc[n].z *= c1; Oacc[n].w *= c1;
        }

        // ---- stage P (tf32 bits, warp-private rows) ----
        #pragma unroll
        for (int n = 0; n < 8; n++) {
            Pb0[8 * n + 2 * t]     = f2tf(sacc[n].x);
            Pb0[8 * n + 2 * t + 1] = f2tf(sacc[n].y);
            Pb1[8 * n + 2 * t]     = f2tf(sacc[n].z);
            Pb1[8 * n + 2 * t + 1] = f2tf(sacc[n].w);
        }
        __syncwarp();

        // ---- O += P V  (tf32 single-pass, 64 mma) ----
        #pragma unroll
        for (int sp = 0; sp < 8; sp++) {
            unsigned a0 = Pb0[8 * sp + t];
            unsigned a1 = Pb1[8 * sp + t];
            unsigned a2 = Pb0[8 * sp + t + 4];
            unsigned a3 = Pb1[8 * sp + t + 4];
            #pragma unroll
            for (int n = 0; n < 8; n++) {
                unsigned b0 = Vsu[(8 * sp + t) * VP + 8 * n + g];
                unsigned b1 = Vsu[(8 * sp + t + 4) * VP + 8 * n + g];
                mma8(Oacc[n], a0, a1, a2, a3, b0, b1);
            }
        }
        __syncwarp();
    }

    // ---- normalize + write out [b][s][h*64+d] ----
    const int b_ = bh >> 3, h = bh & 7;
    const float inv0 = 1.0f / l0r, inv1 = 1.0f / l1r;
    float* op0 = out + ((size_t)b_ * SS + (i0 + rbase + g)) * EE + h * HD;
    float* op1 = out + ((size_t)b_ * SS + (i0 + rbase + g + 8)) * EE + h * HD;
    #pragma unroll
    for (int n = 0; n < 8; n++) {
        *(float2*)&op0[8 * n + 2 * t] = make_float2(Oacc[n].x * inv0, Oacc[n].y * inv0);
        *(float2*)&op1[8 * n + 2 * t] = make_float2(Oacc[n].z * inv1, Oacc[n].w * inv1);
    }
}

// ---------------------------------------------------------------------------
// Kernel 3: in-place LayerNorm over E=512 per (b,s) row.
// ---------------------------------------------------------------------------
__global__ void __launch_bounds__(256) ln_kernel(
    float* __restrict__ out,
    const float* __restrict__ gamma,
    const float* __restrict__ beta)
{
    __shared__ float red[16];
    const int row = blockIdx.x;
    float* p = out + (size_t)row * EE;
    const int tid = threadIdx.x;

    float v0 = p[tid], v1 = p[tid + 256];
    float s = v0 + v1;
    float q = v0 * v0 + v1 * v1;
    #pragma unroll
    for (int off = 16; off > 0; off >>= 1) {
        s += __shfl_xor_sync(0xffffffffu, s, off);
        q += __shfl_xor_sync(0xffffffffu, q, off);
    }
    const int wid = tid >> 5, lid = tid & 31;
    if (lid == 0) { red[wid] = s; red[8 + wid] = q; }
    __syncthreads();
    s = 0.0f; q = 0.0f;
    #pragma unroll
    for (int w = 0; w < 8; w++) { s += red[w]; q += red[8 + w]; }

    float mu = s * (1.0f / EE);
    float var = q * (1.0f / EE) - mu * mu;
    float inv = rsqrtf(var + 1e-5f);
    p[tid]       = (v0 - mu) * inv * gamma[tid]       + beta[tid];
    p[tid + 256] = (v1 - mu) * inv * gamma[tid + 256] + beta[tid + 256];
}

// ---------------------------------------------------------------------------
extern "C" void kernel_launch(void* const* d_in, const int* in_sizes, int n_in,
                              void* d_out, int out_size)
{
    const float* x     = (const float*)d_in[0];
    const float* Wq    = (const float*)d_in[1];
    const float* Wk    = (const float*)d_in[2];
    const float* Wv    = (const float*)d_in[3];
    const float* Er    = (const float*)d_in[4];
    const float* gamma = (const float*)d_in[5];
    const float* beta  = (const float*)d_in[6];
    float* out = (float*)d_out;

    cudaFuncSetAttribute(qk_kernel, cudaFuncAttributeMaxDynamicSharedMemorySize, QKV_SMEM_BYTES);
    cudaFuncSetAttribute(v_kernel, cudaFuncAttributeMaxDynamicSharedMemorySize, QKV_SMEM_BYTES);
    cudaFuncSetAttribute(attn_kernel, cudaFuncAttributeMaxDynamicSharedMemorySize, SMEM_BYTES);

    qk_kernel<<<dim3(EE / 128, (BB * SS) / 128, 2), 256, QKV_SMEM_BYTES>>>(x, Wq, Wk);
    v_kernel<<<dim3(EE / 128, (BB * SS) / 128), 256, QKV_SMEM_BYTES>>>(x, Wv);
    attn_kernel<<<dim3(SS / 64, BB * HH), 128, SMEM_BYTES>>>(Er, out);
    ln_kernel<<<BB * SS, 256>>>(out, gamma, beta);
}

// round 10
// speedup vs baseline: 1.6300x; 1.0400x over previous
#include <cuda_runtime.h>
#include <math.h>

#define BB 4
#define SS 2048
#define EE 512
#define HH 8
#define HD 64
#define SCALE 0.04419417382415922f  /* 512^-0.5 (reference scales by E, not HD) */

// Scratch (static device arrays — allocation rules forbid cudaMalloc)
__device__ float g_q[BB * HH * SS * HD];
__device__ float g_k[BB * HH * SS * HD];
__device__ float g_v[BB * HH * SS * HD];

// ---------------------------------------------------------------------------
// helpers
// ---------------------------------------------------------------------------
__device__ __forceinline__ unsigned f2tf(float x) {
    unsigned r; asm("cvt.rna.tf32.f32 %0, %1;" : "=r"(r) : "f"(x)); return r;
}
__device__ __forceinline__ unsigned pk2(float hi, float lo) {
    unsigned r; asm("cvt.rn.bf16x2.f32 %0, %1, %2;" : "=r"(r) : "f"(hi), "f"(lo)); return r;
}

__device__ __forceinline__ void mma8(float4& c,
    unsigned a0, unsigned a1, unsigned a2, unsigned a3, unsigned b0, unsigned b1)
{
    asm("mma.sync.aligned.m16n8k8.row.col.f32.tf32.tf32.f32 "
        "{%0,%1,%2,%3}, {%4,%5,%6,%7}, {%8,%9}, {%0,%1,%2,%3};"
        : "+f"(c.x), "+f"(c.y), "+f"(c.z), "+f"(c.w)
        : "r"(a0), "r"(a1), "r"(a2), "r"(a3), "r"(b0), "r"(b1));
}
__device__ __forceinline__ void mma16(float4& c,
    unsigned a0, unsigned a1, unsigned a2, unsigned a3, unsigned b0, unsigned b1)
{
    asm("mma.sync.aligned.m16n8k16.row.col.f32.bf16.bf16.f32 "
        "{%0,%1,%2,%3}, {%4,%5,%6,%7}, {%8,%9}, {%0,%1,%2,%3};"
        : "+f"(c.x), "+f"(c.y), "+f"(c.z), "+f"(c.w)
        : "r"(a0), "r"(a1), "r"(a2), "r"(a3), "r"(b0), "r"(b1));
}
__device__ __forceinline__ void cpa16(float* dst, const float* src) {
    unsigned sa = (unsigned)__cvta_generic_to_shared(dst);
    asm volatile("cp.async.cg.shared.global [%0], [%1], 16;" :: "r"(sa), "l"(src));
}
#define CP_COMMIT() asm volatile("cp.async.commit_group;")
#define CP_WAIT(n)  asm volatile("cp.async.wait_group %0;" :: "n"(n))

// ---------------------------------------------------------------------------
// Kernel 1: QKV projection — all tf32 single-pass m16n8k8, occupancy 2.
// V input rounding (~1.7e-4) passes linearly to output; budget holds.
// CTA 128x128, 8 warps, warp 64x32, K=32 panels double-buffered cp.async.
// ---------------------------------------------------------------------------
#define QKV_SMEM_BYTES (18432 * 4)

__global__ void __launch_bounds__(256, 2) qkv_kernel(
    const float* __restrict__ x, const float* __restrict__ Wq,
    const float* __restrict__ Wk, const float* __restrict__ Wv)
{
    extern __shared__ float sm[];
    const int z = blockIdx.z;
    const float* W = z == 0 ? Wq : (z == 1 ? Wk : Wv);
    float* outp = z == 0 ? g_q : (z == 1 ? g_k : g_v);
    const int m0 = blockIdx.y * 128, n0 = blockIdx.x * 128;
    const int tid = threadIdx.x, lane = tid & 31, warp = tid >> 5;
    const int g = lane >> 2, t = lane & 3;
    const int mw = (warp >> 2) * 64, nw = (warp & 3) * 32;

    float* Xs[2] = { sm, sm + 4608 };
    float* Ws[2] = { sm + 9216, sm + 13824 };
    const int r_ = tid >> 1, c_ = (tid & 1) * 16;
    #define STAGE(buf, k0) do { \
        cpa16(Xs[buf] + r_ * 36 + c_,      &x[(size_t)(m0 + r_) * EE + (k0) + c_]); \
        cpa16(Xs[buf] + r_ * 36 + c_ + 4,  &x[(size_t)(m0 + r_) * EE + (k0) + c_ + 4]); \
        cpa16(Xs[buf] + r_ * 36 + c_ + 8,  &x[(size_t)(m0 + r_) * EE + (k0) + c_ + 8]); \
        cpa16(Xs[buf] + r_ * 36 + c_ + 12, &x[(size_t)(m0 + r_) * EE + (k0) + c_ + 12]); \
        cpa16(Ws[buf] + r_ * 36 + c_,      &W[(size_t)(n0 + r_) * EE + (k0) + c_]); \
        cpa16(Ws[buf] + r_ * 36 + c_ + 4,  &W[(size_t)(n0 + r_) * EE + (k0) + c_ + 4]); \
        cpa16(Ws[buf] + r_ * 36 + c_ + 8,  &W[(size_t)(n0 + r_) * EE + (k0) + c_ + 8]); \
        cpa16(Ws[buf] + r_ * 36 + c_ + 12, &W[(size_t)(n0 + r_) * EE + (k0) + c_ + 12]); \
        CP_COMMIT(); \
    } while (0)

    float4 acc[4][4];
    #pragma unroll
    for (int m = 0; m < 4; m++)
        #pragma unroll
        for (int n = 0; n < 4; n++) acc[m][n] = make_float4(0.f, 0.f, 0.f, 0.f);

    STAGE(0, 0);
    for (int p = 0; p < 16; p++) {
        if (p < 15) STAGE((p + 1) & 1, (p + 1) * 32);
        if (p < 15) { CP_WAIT(1); } else { CP_WAIT(0); }
        __syncthreads();
        const float* Xb = Xs[p & 1];
        const float* Wb = Ws[p & 1];
        #pragma unroll
        for (int s = 0; s < 4; s++) {
            unsigned a[4][4], b[4][2];
            #pragma unroll
            for (int m = 0; m < 4; m++) {
                const float* r0 = &Xb[(mw + 16 * m + g) * 36 + 8 * s];
                const float* r1 = &Xb[(mw + 16 * m + g + 8) * 36 + 8 * s];
                a[m][0] = f2tf(r0[t]); a[m][1] = f2tf(r1[t]);
                a[m][2] = f2tf(r0[t + 4]); a[m][3] = f2tf(r1[t + 4]);
            }
            #pragma unroll
            for (int n = 0; n < 4; n++) {
                const float* w0 = &Wb[(nw + 8 * n + g) * 36 + 8 * s];
                b[n][0] = f2tf(w0[t]); b[n][1] = f2tf(w0[t + 4]);
            }
            #pragma unroll
            for (int m = 0; m < 4; m++)
                #pragma unroll
                for (int n = 0; n < 4; n++)
                    mma8(acc[m][n], a[m][0], a[m][1], a[m][2], a[m][3], b[n][0], b[n][1]);
        }
        __syncthreads();
    }

    #pragma unroll
    for (int m = 0; m < 4; m++) {
        int r0 = m0 + mw + 16 * m + g, r1 = r0 + 8;
        int b0_ = r0 >> 11, s0_ = r0 & 2047;
        int b1_ = r1 >> 11, s1_ = r1 & 2047;
        #pragma unroll
        for (int n = 0; n < 4; n++) {
            int col = n0 + nw + 8 * n + 2 * t;
            int h = col >> 6, d = col & 63;
            *(float2*)&outp[(((size_t)b0_ * HH + h) * SS + s0_) * HD + d] = make_float2(acc[m][n].x, acc[m][n].y);
            *(float2*)&outp[(((size_t)b1_ * HH + h) * SS + s1_) * HD + d] = make_float2(acc[m][n].z, acc[m][n].w);
        }
    }
}

// ---------------------------------------------------------------------------
// Kernel 2: flash attention with relative-position skew — 64-row CTAs,
// 128 threads, 2 CTAs/SM.
//
// Srel[i,j] = q_i . Er[S-1-(i-j)]  (j<=i) | 0 (j=i+1) | q_{i+1} . Er[j-i-2] (j>=i+2)
//
// S, R1, R2: bf16 m16n8k16 single-pass.  PV: tf32 m16n8k8 single-pass.
// ---------------------------------------------------------------------------
#define QP 68
#define KP2 72
#define VP 72
#define WP2 136
#define RP 84
#define SM_Q  0
#define SM_K  4420
#define SM_V  6724
#define SM_W1 11332
#define SM_W2 15684
#define SM_R  20036
#define SM_TOT_FLOATS 25412
#define SMEM_BYTES (SM_TOT_FLOATS * 4)   /* 101648 B -> 2 CTAs/SM */

__global__ void __launch_bounds__(128, 2) attn_kernel(
    const float* __restrict__ Er, float* __restrict__ out)
{
    extern __shared__ float sm[];
    float* Qs   = sm + SM_Q;
    unsigned* Khs = (unsigned*)(sm + SM_K);
    float* Vs   = sm + SM_V;
    unsigned* W1h = (unsigned*)(sm + SM_W1);
    unsigned* W2h = (unsigned*)(sm + SM_W2);
    float* Rscr = sm + SM_R;
    unsigned* Pb = (unsigned*)sm;
    const unsigned* Vsu = (const unsigned*)Vs;

    const int tid  = threadIdx.x;
    const int lane = tid & 31;
    const int warp = tid >> 5;
    const int g = lane >> 2;
    const int t = lane & 3;
    const int rbase = warp * 16;

    const int bh = blockIdx.y;
    const int i0 = blockIdx.x * 64;

    const float* qb0 = g_q + (size_t)bh * SS * HD;
    const float* kb0 = g_k + (size_t)bh * SS * HD;
    const float* vb0 = g_v + (size_t)bh * SS * HD;

    for (int idx = tid; idx < 65 * 16; idx += 128) {
        int r = idx >> 4, dq = (idx & 15) * 4;
        float4 v = make_float4(0.f, 0.f, 0.f, 0.f);
        int gi = i0 + r;
        if (gi < SS) v = *(const float4*)&qb0[(size_t)gi * HD + dq];
        *(float4*)&Qs[r * QP + dq] = v;
    }
    __syncthreads();

    unsigned aq[4][4], aq2[4][4];
    {
        const float* r0 = &Qs[(rbase + g) * QP];
        const float* r1 = &Qs[(rbase + g + 8) * QP];
        const float* s0 = &Qs[(rbase + g + 1) * QP];
        const float* s1 = &Qs[(rbase + g + 9) * QP];
        #pragma unroll
        for (int s = 0; s < 4; s++) {
            float2 f0 = *(const float2*)&r0[16 * s + 2 * t];
            float2 f1 = *(const float2*)&r1[16 * s + 2 * t];
            float2 f2 = *(const float2*)&r0[16 * s + 2 * t + 8];
            float2 f3 = *(const float2*)&r1[16 * s + 2 * t + 8];
            aq[s][0] = pk2(f0.y, f0.x);
            aq[s][1] = pk2(f1.y, f1.x);
            aq[s][2] = pk2(f2.y, f2.x);
            aq[s][3] = pk2(f3.y, f3.x);
            float2 h0 = *(const float2*)&s0[16 * s + 2 * t];
            float2 h1 = *(const float2*)&s1[16 * s + 2 * t];
            float2 h2 = *(const float2*)&s0[16 * s + 2 * t + 8];
            float2 h3 = *(const float2*)&s1[16 * s + 2 * t + 8];
            aq2[s][0] = pk2(h0.y, h0.x);
            aq2[s][1] = pk2(h1.y, h1.x);
            aq2[s][2] = pk2(h2.y, h2.x);
            aq2[s][3] = pk2(h3.y, h3.x);
        }
    }
    __syncthreads();

    float4 Oacc[8];
    #pragma unroll
    for (int n = 0; n < 8; n++) Oacc[n] = make_float4(0.f, 0.f, 0.f, 0.f);
    float m0r = -1e30f, m1r = -1e30f, l0r = 0.f, l1r = 0.f;

    const float* rp0 = &Rscr[(rbase + g) * RP];
    const float* rp1 = &Rscr[(rbase + g + 8) * RP];
    float* wr0 = &Rscr[(rbase + g) * RP + 2 * t];
    float* wr1 = &Rscr[(rbase + g + 8) * RP + 2 * t];
    unsigned* Pb0 = Pb + (rbase + g) * QP;
    unsigned* Pb1 = Pb + (rbase + g + 8) * QP;
    const int off1w = 48 - rbase;
    const int tlb = 2 * t + 15 - g;
    const int diffb = (2 * t) - (i0 + rbase + g);

    for (int j0 = 0; j0 < SS; j0 += 64) {
        __syncthreads();

        const bool need1 = (j0 <= i0 + 63);
        const bool need2 = (j0 + 63 >= i0 + 2);
        const int L1 = SS - 64 - i0 + j0;
        const int L2 = j0 - i0 - 65;

        for (int idx = tid; idx < 64 * 16; idx += 128) {
            int j = idx >> 4, dq = (idx & 15) * 4;
            float4 kv = *(const float4*)&kb0[(size_t)(j0 + j) * HD + dq];
            int d2 = dq >> 1;
            Khs[d2 * KP2 + j]       = pk2(kv.y, kv.x);
            Khs[(d2 + 1) * KP2 + j] = pk2(kv.w, kv.z);
            float4 vv = *(const float4*)&vb0[(size_t)(j0 + j) * HD + dq];
            float4 cv;
            cv.x = __uint_as_float(f2tf(vv.x));
            cv.y = __uint_as_float(f2tf(vv.y));
            cv.z = __uint_as_float(f2tf(vv.z));
            cv.w = __uint_as_float(f2tf(vv.w));
            *(float4*)&Vs[j * VP + dq] = cv;
        }
        if (need1) {
            for (int idx = tid; idx < 128 * 16; idx += 128) {
                int tl = idx >> 4, dq = (idx & 15) * 4;
                int l = L1 + tl;
                float4 e = make_float4(0.f, 0.f, 0.f, 0.f);
                if (l >= 0 && l < SS) e = *(const float4*)&Er[(size_t)l * HD + dq];
                int d2 = dq >> 1;
                W1h[d2 * WP2 + tl]       = pk2(e.y, e.x);
                W1h[(d2 + 1) * WP2 + tl] = pk2(e.w, e.z);
            }
        }
        if (need2) {
            for (int idx = tid; idx < 128 * 16; idx += 128) {
                int tl = idx >> 4, dq = (idx & 15) * 4;
                int l = L2 + tl;
                float4 e = make_float4(0.f, 0.f, 0.f, 0.f);
                if (l >= 0 && l < SS) e = *(const float4*)&Er[(size_t)l * HD + dq];
                int d2 = dq >> 1;
                W2h[d2 * WP2 + tl]       = pk2(e.y, e.x);
                W2h[(d2 + 1) * WP2 + tl] = pk2(e.w, e.z);
            }
        }
        __syncthreads();

        // ---- S = Q K^T (bf16, 32 mma) ----
        float4 sacc[8];
        #pragma unroll
        for (int n = 0; n < 8; n++) {
            float4 c = make_float4(0.f, 0.f, 0.f, 0.f);
            #pragma unroll
            for (int s = 0; s < 4; s++) {
                unsigned b0 = Khs[(8 * s + t) * KP2 + 8 * n + g];
                unsigned b1 = Khs[(8 * s + t + 4) * KP2 + 8 * n + g];
                mma16(c, aq[s][0], aq[s][1], aq[s][2], aq[s][3], b0, b1);
            }
            sacc[n] = c;
        }

        const bool wneed1 = (j0 <= i0 + rbase + 15);
        const bool wneed2 = (j0 + 63 >= i0 + rbase + 2);

        if (wneed1) {
            #pragma unroll
            for (int n = 0; n < 10; n++) {
                float4 c = make_float4(0.f, 0.f, 0.f, 0.f);
                #pragma unroll
                for (int s = 0; s < 4; s++) {
                    unsigned b0 = W1h[(8 * s + t) * WP2 + off1w + 8 * n + g];
                    unsigned b1 = W1h[(8 * s + t + 4) * WP2 + off1w + 8 * n + g];
                    mma16(c, aq[s][0], aq[s][1], aq[s][2], aq[s][3], b0, b1);
                }
                wr0[8 * n] = c.x; wr0[8 * n + 1] = c.y;
                wr1[8 * n] = c.z; wr1[8 * n + 1] = c.w;
            }
            __syncwarp();
            #pragma unroll
            for (int n = 0; n < 8; n++) {
                int d00 = diffb + j0 + 8 * n;
                int tl = tlb + 8 * n;
                if (d00 <= 0)     sacc[n].x += rp0[tl];
                if (d00 + 1 <= 0) sacc[n].y += rp0[tl + 1];
                if (d00 - 8 <= 0) sacc[n].z += rp1[tl - 8];
                if (d00 - 7 <= 0) sacc[n].w += rp1[tl - 7];
            }
            __syncwarp();
        }
        if (wneed2) {
            #pragma unroll
            for (int n = 0; n < 10; n++) {
                float4 c = make_float4(0.f, 0.f, 0.f, 0.f);
                #pragma unroll
                for (int s = 0; s < 4; s++) {
                    unsigned b0 = W2h[(8 * s + t) * WP2 + off1w + 8 * n + g];
                    unsigned b1 = W2h[(8 * s + t + 4) * WP2 + off1w + 8 * n + g];
                    mma16(c, aq2[s][0], aq2[s][1], aq2[s][2], aq2[s][3], b0, b1);
                }
                wr0[8 * n] = c.x; wr0[8 * n + 1] = c.y;
                wr1[8 * n] = c.z; wr1[8 * n + 1] = c.w;
            }
            __syncwarp();
            #pragma unroll
            for (int n = 0; n < 8; n++) {
                int d00 = diffb + j0 + 8 * n;
                int tl = tlb + 8 * n;
                if (d00 >= 2)     sacc[n].x += rp0[tl];
                if (d00 + 1 >= 2) sacc[n].y += rp0[tl + 1];
                if (d00 - 8 >= 2) sacc[n].z += rp1[tl - 8];
                if (d00 - 7 >= 2) sacc[n].w += rp1[tl - 7];
            }
            __syncwarp();
        }

        // ---- scale + online softmax ----
        float mx0 = -1e30f, mx1 = -1e30f;
        #pragma unroll
        for (int n = 0; n < 8; n++) {
            sacc[n].x *= SCALE; sacc[n].y *= SCALE;
            sacc[n].z *= SCALE; sacc[n].w *= SCALE;
            mx0 = fmaxf(mx0, fmaxf(sacc[n].x, sacc[n].y));
            mx1 = fmaxf(mx1, fmaxf(sacc[n].z, sacc[n].w));
        }
        #pragma unroll
        for (int off = 1; off <= 2; off <<= 1) {
            mx0 = fmaxf(mx0, __shfl_xor_sync(0xffffffffu, mx0, off));
            mx1 = fmaxf(mx1, __shfl_xor_sync(0xffffffffu, mx1, off));
        }
        float mn0 = fmaxf(m0r, mx0), mn1 = fmaxf(m1r, mx1);
        float c0 = __expf(m0r - mn0), c1 = __expf(m1r - mn1);
        float rs0 = 0.f, rs1 = 0.f;
        #pragma unroll
        for (int n = 0; n < 8; n++) {
            sacc[n].x = __expf(sacc[n].x - mn0);
            sacc[n].y = __expf(sacc[n].y - mn0);
            sacc[n].z = __expf(sacc[n].z - mn1);
            sacc[n].w = __expf(sacc[n].w - mn1);
            rs0 += sacc[n].x + sacc[n].y;
            rs1 += sacc[n].z + sacc[n].w;
        }
        #pragma unroll
        for (int off = 1; off <= 2; off <<= 1) {
            rs0 += __shfl_xor_sync(0xffffffffu, rs0, off);
            rs1 += __shfl_xor_sync(0xffffffffu, rs1, off);
        }
        l0r = l0r * c0 + rs0;  m0r = mn0;
        l1r = l1r * c1 + rs1;  m1r = mn1;
        #pragma unroll
        for (int n = 0; n < 8; n++) {
            Oacc[n].x *= c0; Oacc[n].y *= c0;
            Oacc[n].z *= c1; Oacc[n].w *= c1;
        }

        // ---- stage P (tf32 bits, warp-private rows) ----
        #pragma unroll
        for (int n = 0; n < 8; n++) {
            Pb0[8 * n + 2 * t]     = f2tf(sacc[n].x);
            Pb0[8 * n + 2 * t + 1] = f2tf(sacc[n].y);
            Pb1[8 * n + 2 * t]     = f2tf(sacc[n].z);
            Pb1[8 * n + 2 * t + 1] = f2tf(sacc[n].w);
        }
        __syncwarp();

        // ---- O += P V  (tf32 single-pass, 64 mma) ----
        #pragma unroll
        for (int sp = 0; sp < 8; sp++) {
            unsigned a0 = Pb0[8 * sp + t];
            unsigned a1 = Pb1[8 * sp + t];
            unsigned a2 = Pb0[8 * sp + t + 4];
            unsigned a3 = Pb1[8 * sp + t + 4];
            #pragma unroll
            for (int n = 0; n < 8; n++) {
                unsigned b0 = Vsu[(8 * sp + t) * VP + 8 * n + g];
                unsigned b1 = Vsu[(8 * sp + t + 4) * VP + 8 * n + g];
                mma8(Oacc[n], a0, a1, a2, a3, b0, b1);
            }
        }
        __syncwarp();
    }

    // ---- normalize + write out [b][s][h*64+d] ----
    const int b_ = bh >> 3, h = bh & 7;
    const float inv0 = 1.0f / l0r, inv1 = 1.0f / l1r;
    float* op0 = out + ((size_t)b_ * SS + (i0 + rbase + g)) * EE + h * HD;
    float* op1 = out + ((size_t)b_ * SS + (i0 + rbase + g + 8)) * EE + h * HD;
    #pragma unroll
    for (int n = 0; n < 8; n++) {
        *(float2*)&op0[8 * n + 2 * t] = make_float2(Oacc[n].x * inv0, Oacc[n].y * inv0);
        *(float2*)&op1[8 * n + 2 * t] = make_float2(Oacc[n].z * inv1, Oacc[n].w * inv1);
    }
}

// ---------------------------------------------------------------------------
// Kernel 3: in-place LayerNorm over E=512 per (b,s) row.
// ---------------------------------------------------------------------------
__global__ void __launch_bounds__(256) ln_kernel(
    float* __restrict__ out,
    const float* __restrict__ gamma,
    const float* __restrict__ beta)
{
    __shared__ float red[16];
    const int row = blockIdx.x;
    float* p = out + (size_t)row * EE;
    const int tid = threadIdx.x;

    float v0 = p[tid], v1 = p[tid + 256];
    float s = v0 + v1;
    float q = v0 * v0 + v1 * v1;
    #pragma unroll
    for (int off = 16; off > 0; off >>= 1) {
        s += __shfl_xor_sync(0xffffffffu, s, off);
        q += __shfl_xor_sync(0xffffffffu, q, off);
    }
    const int wid = tid >> 5, lid = tid & 31;
    if (lid == 0) { red[wid] = s; red[8 + wid] = q; }
    __syncthreads();
    s = 0.0f; q = 0.0f;
    #pragma unroll
    for (int w = 0; w < 8; w++) { s += red[w]; q += red[8 + w]; }

    float mu = s * (1.0f / EE);
    float var = q * (1.0f / EE) - mu * mu;
    float inv = rsqrtf(var + 1e-5f);
    p[tid]       = (v0 - mu) * inv * gamma[tid]       + beta[tid];
    p[tid + 256] = (v1 - mu) * inv * gamma[tid + 256] + beta[tid + 256];
}

// ---------------------------------------------------------------------------
extern "C" void kernel_launch(void* const* d_in, const int* in_sizes, int n_in,
                              void* d_out, int out_size)
{
    const float* x     = (const float*)d_in[0];
    const float* Wq    = (const float*)d_in[1];
    const float* Wk    = (const float*)d_in[2];
    const float* Wv    = (const float*)d_in[3];
    const float* Er    = (const float*)d_in[4];
    const float* gamma = (const float*)d_in[5];
    const float* beta  = (const float*)d_in[6];
    float* out = (float*)d_out;

    cudaFuncSetAttribute(qkv_kernel, cudaFuncAttributeMaxDynamicSharedMemorySize, QKV_SMEM_BYTES);
    cudaFuncSetAttribute(attn_kernel, cudaFuncAttributeMaxDynamicSharedMemorySize, SMEM_BYTES);

    qkv_kernel<<<dim3(EE / 128, (BB * SS) / 128, 3), 256, QKV_SMEM_BYTES>>>(x, Wq, Wk, Wv);
    attn_kernel<<<dim3(SS / 64, BB * HH), 128, SMEM_BYTES>>>(Er, out);
    ln_kernel<<<BB * SS, 256>>>(out, gamma, beta);
}

// round 11
// speedup vs baseline: 2.2149x; 1.3588x over previous
#include <cuda_runtime.h>
#include <math.h>

#define BB 4
#define SS 2048
#define EE 512
#define HH 8
#define HD 64
#define SCALE 0.04419417382415922f  /* 512^-0.5 (reference scales by E, not HD) */
#define ERBW 6656
#define EROFF 2056

// Scratch (static device arrays — allocation rules forbid cudaMalloc)
__device__ float    g_q [BB * HH * SS * HD];           // fp32 Q
__device__ unsigned g_kb[(size_t)BB * HH * 32 * SS];   // bf16x2-packed K [bh][d2][s]
__device__ float    g_vt[(size_t)BB * HH * SS * HD];   // tf32-bits V [bh][s][d]
__device__ unsigned g_erb[32 * ERBW];                  // bf16x2 Er [d2][EROFF+l], zero-padded

// ---------------------------------------------------------------------------
// helpers
// ---------------------------------------------------------------------------
__device__ __forceinline__ unsigned f2tf(float x) {
    unsigned r; asm("cvt.rna.tf32.f32 %0, %1;" : "=r"(r) : "f"(x)); return r;
}
__device__ __forceinline__ unsigned pk2(float hi, float lo) {
    unsigned r; asm("cvt.rn.bf16x2.f32 %0, %1, %2;" : "=r"(r) : "f"(hi), "f"(lo)); return r;
}

__device__ __forceinline__ void mma8(float4& c,
    unsigned a0, unsigned a1, unsigned a2, unsigned a3, unsigned b0, unsigned b1)
{
    asm("mma.sync.aligned.m16n8k8.row.col.f32.tf32.tf32.f32 "
        "{%0,%1,%2,%3}, {%4,%5,%6,%7}, {%8,%9}, {%0,%1,%2,%3};"
        : "+f"(c.x), "+f"(c.y), "+f"(c.z), "+f"(c.w)
        : "r"(a0), "r"(a1), "r"(a2), "r"(a3), "r"(b0), "r"(b1));
}
__device__ __forceinline__ void mma16(float4& c,
    unsigned a0, unsigned a1, unsigned a2, unsigned a3, unsigned b0, unsigned b1)
{
    asm("mma.sync.aligned.m16n8k16.row.col.f32.bf16.bf16.f32 "
        "{%0,%1,%2,%3}, {%4,%5,%6,%7}, {%8,%9}, {%0,%1,%2,%3};"
        : "+f"(c.x), "+f"(c.y), "+f"(c.z), "+f"(c.w)
        : "r"(a0), "r"(a1), "r"(a2), "r"(a3), "r"(b0), "r"(b1));
}
__device__ __forceinline__ void cpa16(float* dst, const float* src) {
    unsigned sa = (unsigned)__cvta_generic_to_shared(dst);
    asm volatile("cp.async.cg.shared.global [%0], [%1], 16;" :: "r"(sa), "l"(src));
}
#define CP_COMMIT() asm volatile("cp.async.commit_group;")
#define CP_WAIT(n)  asm volatile("cp.async.wait_group %0;" :: "n"(n))

// ---------------------------------------------------------------------------
// Kernel 0: pack Er into zero-padded bf16x2 rows [d2][EROFF + l].
// Padding is never written; __device__ zero-init makes OOB reads free zeros.
// ---------------------------------------------------------------------------
__global__ void __launch_bounds__(256) erb_kernel(const float* __restrict__ Er)
{
    int idx = blockIdx.x * 256 + threadIdx.x;   // 65536 = 32 d2 x 2048 l
    int d2 = idx >> 11, l = idx & 2047;
    float2 e = *(const float2*)&Er[(size_t)l * HD + 2 * d2];
    g_erb[d2 * ERBW + EROFF + l] = pk2(e.y, e.x);
}

// ---------------------------------------------------------------------------
// Kernel 1: QKV projection — all tf32 single-pass m16n8k8, occupancy 2.
//   z=0: Q fp32 [bh][s][d].  z=1: K packed bf16x2 [bh][d2][s].
//   z=2: V tf32-bits [bh][s][d].
// ---------------------------------------------------------------------------
#define QKV_SMEM_BYTES (18432 * 4)

__global__ void __launch_bounds__(256, 2) qkv_kernel(
    const float* __restrict__ x, const float* __restrict__ Wq,
    const float* __restrict__ Wk, const float* __restrict__ Wv)
{
    extern __shared__ float sm[];
    const int z = blockIdx.z;
    const float* W = z == 0 ? Wq : (z == 1 ? Wk : Wv);
    const int m0 = blockIdx.y * 128, n0 = blockIdx.x * 128;
    const int tid = threadIdx.x, lane = tid & 31, warp = tid >> 5;
    const int g = lane >> 2, t = lane & 3;
    const int mw = (warp >> 2) * 64, nw = (warp & 3) * 32;

    float* Xs[2] = { sm, sm + 4608 };
    float* Ws[2] = { sm + 9216, sm + 13824 };
    const int r_ = tid >> 1, c_ = (tid & 1) * 16;
    #define STAGE(buf, k0) do { \
        cpa16(Xs[buf] + r_ * 36 + c_,      &x[(size_t)(m0 + r_) * EE + (k0) + c_]); \
        cpa16(Xs[buf] + r_ * 36 + c_ + 4,  &x[(size_t)(m0 + r_) * EE + (k0) + c_ + 4]); \
        cpa16(Xs[buf] + r_ * 36 + c_ + 8,  &x[(size_t)(m0 + r_) * EE + (k0) + c_ + 8]); \
        cpa16(Xs[buf] + r_ * 36 + c_ + 12, &x[(size_t)(m0 + r_) * EE + (k0) + c_ + 12]); \
        cpa16(Ws[buf] + r_ * 36 + c_,      &W[(size_t)(n0 + r_) * EE + (k0) + c_]); \
        cpa16(Ws[buf] + r_ * 36 + c_ + 4,  &W[(size_t)(n0 + r_) * EE + (k0) + c_ + 4]); \
        cpa16(Ws[buf] + r_ * 36 + c_ + 8,  &W[(size_t)(n0 + r_) * EE + (k0) + c_ + 8]); \
        cpa16(Ws[buf] + r_ * 36 + c_ + 12, &W[(size_t)(n0 + r_) * EE + (k0) + c_ + 12]); \
        CP_COMMIT(); \
    } while (0)

    float4 acc[4][4];
    #pragma unroll
    for (int m = 0; m < 4; m++)
        #pragma unroll
        for (int n = 0; n < 4; n++) acc[m][n] = make_float4(0.f, 0.f, 0.f, 0.f);

    STAGE(0, 0);
    for (int p = 0; p < 16; p++) {
        if (p < 15) STAGE((p + 1) & 1, (p + 1) * 32);
        if (p < 15) { CP_WAIT(1); } else { CP_WAIT(0); }
        __syncthreads();
        const float* Xb = Xs[p & 1];
        const float* Wb = Ws[p & 1];
        #pragma unroll
        for (int s = 0; s < 4; s++) {
            unsigned a[4][4], b[4][2];
            #pragma unroll
            for (int m = 0; m < 4; m++) {
                const float* r0 = &Xb[(mw + 16 * m + g) * 36 + 8 * s];
                const float* r1 = &Xb[(mw + 16 * m + g + 8) * 36 + 8 * s];
                a[m][0] = f2tf(r0[t]); a[m][1] = f2tf(r1[t]);
                a[m][2] = f2tf(r0[t + 4]); a[m][3] = f2tf(r1[t + 4]);
            }
            #pragma unroll
            for (int n = 0; n < 4; n++) {
                const float* w0 = &Wb[(nw + 8 * n + g) * 36 + 8 * s];
                b[n][0] = f2tf(w0[t]); b[n][1] = f2tf(w0[t + 4]);
            }
            #pragma unroll
            for (int m = 0; m < 4; m++)
                #pragma unroll
                for (int n = 0; n < 4; n++)
                    mma8(acc[m][n], a[m][0], a[m][1], a[m][2], a[m][3], b[n][0], b[n][1]);
        }
        __syncthreads();
    }

    #pragma unroll
    for (int m = 0; m < 4; m++) {
        int r0 = m0 + mw + 16 * m + g, r1 = r0 + 8;
        int b0_ = r0 >> 11, s0_ = r0 & 2047;
        int b1_ = r1 >> 11, s1_ = r1 & 2047;
        #pragma unroll
        for (int n = 0; n < 4; n++) {
            int col = n0 + nw + 8 * n + 2 * t;
            int h = col >> 6, d = col & 63;
            if (z == 0) {
                *(float2*)&g_q[(((size_t)b0_ * HH + h) * SS + s0_) * HD + d] = make_float2(acc[m][n].x, acc[m][n].y);
                *(float2*)&g_q[(((size_t)b1_ * HH + h) * SS + s1_) * HD + d] = make_float2(acc[m][n].z, acc[m][n].w);
            } else if (z == 1) {
                int d2 = d >> 1;
                g_kb[((size_t)(b0_ * HH + h) * 32 + d2) * SS + s0_] = pk2(acc[m][n].y, acc[m][n].x);
                g_kb[((size_t)(b1_ * HH + h) * 32 + d2) * SS + s1_] = pk2(acc[m][n].w, acc[m][n].z);
            } else {
                *(float2*)&g_vt[(((size_t)b0_ * HH + h) * SS + s0_) * HD + d] =
                    make_float2(__uint_as_float(f2tf(acc[m][n].x)), __uint_as_float(f2tf(acc[m][n].y)));
                *(float2*)&g_vt[(((size_t)b1_ * HH + h) * SS + s1_) * HD + d] =
                    make_float2(__uint_as_float(f2tf(acc[m][n].z)), __uint_as_float(f2tf(acc[m][n].w)));
            }
        }
    }
}

// ---------------------------------------------------------------------------
// Kernel 2: flash attention with relative-position skew — 64-row CTAs,
// 128 threads, 2 CTAs/SM. Staging is pure copy (operands pre-packed).
//
// Srel[i,j] = q_i . Er[S-1-(i-j)]  (j<=i) | 0 (j=i+1) | q_{i+1} . Er[j-i-2] (j>=i+2)
//
// S, R1, R2: bf16 m16n8k16 single-pass.  PV: tf32 m16n8k8 single-pass.
// ---------------------------------------------------------------------------
#define QP 68
#define KP2 72
#define VP 72
#define WP2 136
#define RP 84
#define SM_Q  0
#define SM_K  4420
#define SM_V  6724
#define SM_W1 11332
#define SM_W2 15684
#define SM_R  20036
#define SM_TOT_FLOATS 25412
#define SMEM_BYTES (SM_TOT_FLOATS * 4)   /* 101648 B -> 2 CTAs/SM */

__global__ void __launch_bounds__(128, 2) attn_kernel(float* __restrict__ out)
{
    extern __shared__ float sm[];
    float* Qs   = sm + SM_Q;
    unsigned* Khs = (unsigned*)(sm + SM_K);
    float* Vs   = sm + SM_V;
    unsigned* W1h = (unsigned*)(sm + SM_W1);
    unsigned* W2h = (unsigned*)(sm + SM_W2);
    float* Rscr = sm + SM_R;
    unsigned* Pb = (unsigned*)sm;
    const unsigned* Vsu = (const unsigned*)Vs;

    const int tid  = threadIdx.x;
    const int lane = tid & 31;
    const int warp = tid >> 5;
    const int g = lane >> 2;
    const int t = lane & 3;
    const int rbase = warp * 16;

    const int bh = blockIdx.y;
    const int i0 = blockIdx.x * 64;

    const float* qb0 = g_q + (size_t)bh * SS * HD;
    const unsigned* kbb = g_kb + (size_t)bh * 32 * SS;
    const float* vb0 = g_vt + (size_t)bh * SS * HD;

    for (int idx = tid; idx < 65 * 16; idx += 128) {
        int r = idx >> 4, dq = (idx & 15) * 4;
        float4 v = make_float4(0.f, 0.f, 0.f, 0.f);
        int gi = i0 + r;
        if (gi < SS) v = *(const float4*)&qb0[(size_t)gi * HD + dq];
        *(float4*)&Qs[r * QP + dq] = v;
    }
    __syncthreads();

    unsigned aq[4][4], aq2[4][4];
    {
        const float* r0 = &Qs[(rbase + g) * QP];
        const float* r1 = &Qs[(rbase + g + 8) * QP];
        const float* s0 = &Qs[(rbase + g + 1) * QP];
        const float* s1 = &Qs[(rbase + g + 9) * QP];
        #pragma unroll
        for (int s = 0; s < 4; s++) {
            float2 f0 = *(const float2*)&r0[16 * s + 2 * t];
            float2 f1 = *(const float2*)&r1[16 * s + 2 * t];
            float2 f2 = *(const float2*)&r0[16 * s + 2 * t + 8];
            float2 f3 = *(const float2*)&r1[16 * s + 2 * t + 8];
            aq[s][0] = pk2(f0.y, f0.x);
            aq[s][1] = pk2(f1.y, f1.x);
            aq[s][2] = pk2(f2.y, f2.x);
            aq[s][3] = pk2(f3.y, f3.x);
            float2 h0 = *(const float2*)&s0[16 * s + 2 * t];
            float2 h1 = *(const float2*)&s1[16 * s + 2 * t];
            float2 h2 = *(const float2*)&s0[16 * s + 2 * t + 8];
            float2 h3 = *(const float2*)&s1[16 * s + 2 * t + 8];
            aq2[s][0] = pk2(h0.y, h0.x);
            aq2[s][1] = pk2(h1.y, h1.x);
            aq2[s][2] = pk2(h2.y, h2.x);
            aq2[s][3] = pk2(h3.y, h3.x);
        }
    }
    __syncthreads();  // frag build done before Pb overwrites Qs

    float4 Oacc[8];
    #pragma unroll
    for (int n = 0; n < 8; n++) Oacc[n] = make_float4(0.f, 0.f, 0.f, 0.f);
    float m0r = -1e30f, m1r = -1e30f, l0r = 0.f, l1r = 0.f;

    const float* rp0 = &Rscr[(rbase + g) * RP];
    const float* rp1 = &Rscr[(rbase + g + 8) * RP];
    float* wr0 = &Rscr[(rbase + g) * RP + 2 * t];
    float* wr1 = &Rscr[(rbase + g + 8) * RP + 2 * t];
    unsigned* Pb0 = Pb + (rbase + g) * QP;
    unsigned* Pb1 = Pb + (rbase + g + 8) * QP;
    const int off1w = 48 - rbase;
    const int tlb = 2 * t + 15 - g;
    const int diffb = (2 * t) - (i0 + rbase + g);

    for (int j0 = 0; j0 < SS; j0 += 64) {
        __syncthreads();

        const bool need1 = (j0 <= i0 + 63);
        const bool need2 = (j0 + 63 >= i0 + 2);
        const int L1 = SS - 64 - i0 + j0;
        const int L2 = j0 - i0 - 65;

        // ---- staging: pure copies (operands pre-packed) ----
        #pragma unroll
        for (int ii = 0; ii < 16; ii++) {
            int idx = tid + ii * 128;           // 2048: K packed rows
            int d2 = idx >> 6, j = idx & 63;
            Khs[d2 * KP2 + j] = kbb[(size_t)d2 * SS + j0 + j];
        }
        #pragma unroll
        for (int ii = 0; ii < 8; ii++) {
            int idx = tid + ii * 128;           // 1024: V float4 rows
            int j = idx >> 4, dq = (idx & 15) * 4;
            *(float4*)&Vs[j * VP + dq] = *(const float4*)&vb0[(size_t)(j0 + j) * HD + dq];
        }
        if (need1) {
            #pragma unroll
            for (int ii = 0; ii < 32; ii++) {
                int idx = tid + ii * 128;       // 4096: W1 rows of 128
                int d2 = idx >> 7, tl = idx & 127;
                W1h[d2 * WP2 + tl] = g_erb[d2 * ERBW + EROFF + L1 + tl];
            }
        }
        if (need2) {
            #pragma unroll
            for (int ii = 0; ii < 32; ii++) {
                int idx = tid + ii * 128;
                int d2 = idx >> 7, tl = idx & 127;
                W2h[d2 * WP2 + tl] = g_erb[d2 * ERBW + EROFF + L2 + tl];
            }
        }
        __syncthreads();

        // ---- S = Q K^T (bf16, 32 mma) ----
        float4 sacc[8];
        #pragma unroll
        for (int n = 0; n < 8; n++) {
            float4 c = make_float4(0.f, 0.f, 0.f, 0.f);
            #pragma unroll
            for (int s = 0; s < 4; s++) {
                unsigned b0 = Khs[(8 * s + t) * KP2 + 8 * n + g];
                unsigned b1 = Khs[(8 * s + t + 4) * KP2 + 8 * n + g];
                mma16(c, aq[s][0], aq[s][1], aq[s][2], aq[s][3], b0, b1);
            }
            sacc[n] = c;
        }

        const bool wneed1 = (j0 <= i0 + rbase + 15);
        const bool wneed2 = (j0 + 63 >= i0 + rbase + 2);

        if (wneed1) {
            #pragma unroll
            for (int n = 0; n < 10; n++) {
                float4 c = make_float4(0.f, 0.f, 0.f, 0.f);
                #pragma unroll
                for (int s = 0; s < 4; s++) {
                    unsigned b0 = W1h[(8 * s + t) * WP2 + off1w + 8 * n + g];
                    unsigned b1 = W1h[(8 * s + t + 4) * WP2 + off1w + 8 * n + g];
                    mma16(c, aq[s][0], aq[s][1], aq[s][2], aq[s][3], b0, b1);
                }
                wr0[8 * n] = c.x; wr0[8 * n + 1] = c.y;
                wr1[8 * n] = c.z; wr1[8 * n + 1] = c.w;
            }
            __syncwarp();
            #pragma unroll
            for (int n = 0; n < 8; n++) {
                int d00 = diffb + j0 + 8 * n;
                int tl = tlb + 8 * n;
                if (d00 <= 0)     sacc[n].x += rp0[tl];
                if (d00 + 1 <= 0) sacc[n].y += rp0[tl + 1];
                if (d00 - 8 <= 0) sacc[n].z += rp1[tl - 8];
                if (d00 - 7 <= 0) sacc[n].w += rp1[tl - 7];
            }
            __syncwarp();
        }
        if (wneed2) {
            #pragma unroll
            for (int n = 0; n < 10; n++) {
                float4 c = make_float4(0.f, 0.f, 0.f, 0.f);
                #pragma unroll
                for (int s = 0; s < 4; s++) {
                    unsigned b0 = W2h[(8 * s + t) * WP2 + off1w + 8 * n + g];
                    unsigned b1 = W2h[(8 * s + t + 4) * WP2 + off1w + 8 * n + g];
                    mma16(c, aq2[s][0], aq2[s][1], aq2[s][2], aq2[s][3], b0, b1);
                }
                wr0[8 * n] = c.x; wr0[8 * n + 1] = c.y;
                wr1[8 * n] = c.z; wr1[8 * n + 1] = c.w;
            }
            __syncwarp();
            #pragma unroll
            for (int n = 0; n < 8; n++) {
                int d00 = diffb + j0 + 8 * n;
                int tl = tlb + 8 * n;
                if (d00 >= 2)     sacc[n].x += rp0[tl];
                if (d00 + 1 >= 2) sacc[n].y += rp0[tl + 1];
                if (d00 - 8 >= 2) sacc[n].z += rp1[tl - 8];
                if (d00 - 7 >= 2) sacc[n].w += rp1[tl - 7];
            }
            __syncwarp();
        }

        // ---- scale + online softmax ----
        float mx0 = -1e30f, mx1 = -1e30f;
        #pragma unroll
        for (int n = 0; n < 8; n++) {
            sacc[n].x *= SCALE; sacc[n].y *= SCALE;
            sacc[n].z *= SCALE; sacc[n].w *= SCALE;
            mx0 = fmaxf(mx0, fmaxf(sacc[n].x, sacc[n].y));
            mx1 = fmaxf(mx1, fmaxf(sacc[n].z, sacc[n].w));
        }
        #pragma unroll
        for (int off = 1; off <= 2; off <<= 1) {
            mx0 = fmaxf(mx0, __shfl_xor_sync(0xffffffffu, mx0, off));
            mx1 = fmaxf(mx1, __shfl_xor_sync(0xffffffffu, mx1, off));
        }
        float mn0 = fmaxf(m0r, mx0), mn1 = fmaxf(m1r, mx1);
        float c0 = __expf(m0r - mn0), c1 = __expf(m1r - mn1);
        float rs0 = 0.f, rs1 = 0.f;
        #pragma unroll
        for (int n = 0; n < 8; n++) {
            sacc[n].x = __expf(sacc[n].x - mn0);
            sacc[n].y = __expf(sacc[n].y - mn0);
            sacc[n].z = __expf(sacc[n].z - mn1);
            sacc[n].w = __expf(sacc[n].w - mn1);
            rs0 += sacc[n].x + sacc[n].y;
            rs1 += sacc[n].z + sacc[n].w;
        }
        #pragma unroll
        for (int off = 1; off <= 2; off <<= 1) {
            rs0 += __shfl_xor_sync(0xffffffffu, rs0, off);
            rs1 += __shfl_xor_sync(0xffffffffu, rs1, off);
        }
        l0r = l0r * c0 + rs0;  m0r = mn0;
        l1r = l1r * c1 + rs1;  m1r = mn1;
        #pragma unroll
        for (int n = 0; n < 8; n++) {
            Oacc[n].x *= c0; Oacc[n].y *= c0;
            Oacc[n].z *= c1; Oacc[n].w *= c1;
        }

        // ---- stage P (tf32 bits, warp-private rows) ----
        #pragma unroll
        for (int n = 0; n < 8; n++) {
            Pb0[8 * n + 2 * t]     = f2tf(sacc[n].x);
            Pb0[8 * n + 2 * t + 1] = f2tf(sacc[n].y);
            Pb1[8 * n + 2 * t]     = f2tf(sacc[n].z);
            Pb1[8 * n + 2 * t + 1] = f2tf(sacc[n].w);
        }
        __syncwarp();

        // ---- O += P V  (tf32 single-pass, 64 mma) ----
        #pragma unroll
        for (int sp = 0; sp < 8; sp++) {
            unsigned a0 = Pb0[8 * sp + t];
            unsigned a1 = Pb1[8 * sp + t];
            unsigned a2 = Pb0[8 * sp + t + 4];
            unsigned a3 = Pb1[8 * sp + t + 4];
            #pragma unroll
            for (int n = 0; n < 8; n++) {
                unsigned b0 = Vsu[(8 * sp + t) * VP + 8 * n + g];
                unsigned b1 = Vsu[(8 * sp + t + 4) * VP + 8 * n + g];
                mma8(Oacc[n], a0, a1, a2, a3, b0, b1);
            }
        }
        __syncwarp();
    }

    // ---- normalize + write out [b][s][h*64+d] ----
    const int b_ = bh >> 3, h = bh & 7;
    const float inv0 = 1.0f / l0r, inv1 = 1.0f / l1r;
    float* op0 = out + ((size_t)b_ * SS + (i0 + rbase + g)) * EE + h * HD;
    float* op1 = out + ((size_t)b_ * SS + (i0 + rbase + g + 8)) * EE + h * HD;
    #pragma unroll
    for (int n = 0; n < 8; n++) {
        *(float2*)&op0[8 * n + 2 * t] = make_float2(Oacc[n].x * inv0, Oacc[n].y * inv0);
        *(float2*)&op1[8 * n + 2 * t] = make_float2(Oacc[n].z * inv1, Oacc[n].w * inv1);
    }
}

// ---------------------------------------------------------------------------
// Kernel 3: in-place LayerNorm over E=512 per (b,s) row.
// ---------------------------------------------------------------------------
__global__ void __launch_bounds__(256) ln_kernel(
    float* __restrict__ out,
    const float* __restrict__ gamma,
    const float* __restrict__ beta)
{
    __shared__ float red[16];
    const int row = blockIdx.x;
    float* p = out + (size_t)row * EE;
    const int tid = threadIdx.x;

    float v0 = p[tid], v1 = p[tid + 256];
    float s = v0 + v1;
    float q = v0 * v0 + v1 * v1;
    #pragma unroll
    for (int off = 16; off > 0; off >>= 1) {
        s += __shfl_xor_sync(0xffffffffu, s, off);
        q += __shfl_xor_sync(0xffffffffu, q, off);
    }
    const int wid = tid >> 5, lid = tid & 31;
    if (lid == 0) { red[wid] = s; red[8 + wid] = q; }
    __syncthreads();
    s = 0.0f; q = 0.0f;
    #pragma unroll
    for (int w = 0; w < 8; w++) { s += red[w]; q += red[8 + w]; }

    float mu = s * (1.0f / EE);
    float var = q * (1.0f / EE) - mu * mu;
    float inv = rsqrtf(var + 1e-5f);
    p[tid]       = (v0 - mu) * inv * gamma[tid]       + beta[tid];
    p[tid + 256] = (v1 - mu) * inv * gamma[tid + 256] + beta[tid + 256];
}

// ---------------------------------------------------------------------------
extern "C" void kernel_launch(void* const* d_in, const int* in_sizes, int n_in,
                              void* d_out, int out_size)
{
    const float* x     = (const float*)d_in[0];
    const float* Wq    = (const float*)d_in[1];
    const float* Wk    = (const float*)d_in[2];
    const float* Wv    = (const float*)d_in[3];
    const float* Er    = (const float*)d_in[4];
    const float* gamma = (const float*)d_in[5];
    const float* beta  = (const float*)d_in[6];
    float* out = (float*)d_out;

    cudaFuncSetAttribute(qkv_kernel, cudaFuncAttributeMaxDynamicSharedMemorySize, QKV_SMEM_BYTES);
    cudaFuncSetAttribute(attn_kernel, cudaFuncAttributeMaxDynamicSharedMemorySize, SMEM_BYTES);

    erb_kernel<<<256, 256>>>(Er);
    qkv_kernel<<<dim3(EE / 128, (BB * SS) / 128, 3), 256, QKV_SMEM_BYTES>>>(x, Wq, Wk, Wv);
    attn_kernel<<<dim3(SS / 64, BB * HH), 128, SMEM_BYTES>>>(out);
    ln_kernel<<<BB * SS, 256>>>(out, gamma, beta);
}

// round 12
// speedup vs baseline: 2.2261x; 1.0050x over previous
#include <cuda_runtime.h>
#include <math.h>

#define BB 4
#define SS 2048
#define EE 512
#define HH 8
#define HD 64
#define SCALE 0.04419417382415922f  /* 512^-0.5 (reference scales by E, not HD) */
#define ERBW 6656
#define EROFF 2056

// Scratch (static device arrays — allocation rules forbid cudaMalloc)
__device__ float    g_q [BB * HH * SS * HD];           // fp32 Q
__device__ unsigned g_kb[(size_t)BB * HH * 32 * SS];   // bf16x2-packed K [bh][d2][s]
__device__ float    g_vt[(size_t)BB * HH * SS * HD];   // tf32-bits V [bh][s][d]
__device__ unsigned g_erb[32 * ERBW];                  // bf16x2 Er [d2][EROFF+l], zero-padded

// ---------------------------------------------------------------------------
// helpers
// ---------------------------------------------------------------------------
__device__ __forceinline__ unsigned f2tf(float x) {
    unsigned r; asm("cvt.rna.tf32.f32 %0, %1;" : "=r"(r) : "f"(x)); return r;
}
__device__ __forceinline__ unsigned pk2(float hi, float lo) {
    unsigned r; asm("cvt.rn.bf16x2.f32 %0, %1, %2;" : "=r"(r) : "f"(hi), "f"(lo)); return r;
}

__device__ __forceinline__ void mma8(float4& c,
    unsigned a0, unsigned a1, unsigned a2, unsigned a3, unsigned b0, unsigned b1)
{
    asm("mma.sync.aligned.m16n8k8.row.col.f32.tf32.tf32.f32 "
        "{%0,%1,%2,%3}, {%4,%5,%6,%7}, {%8,%9}, {%0,%1,%2,%3};"
        : "+f"(c.x), "+f"(c.y), "+f"(c.z), "+f"(c.w)
        : "r"(a0), "r"(a1), "r"(a2), "r"(a3), "r"(b0), "r"(b1));
}
__device__ __forceinline__ void mma16(float4& c,
    unsigned a0, unsigned a1, unsigned a2, unsigned a3, unsigned b0, unsigned b1)
{
    asm("mma.sync.aligned.m16n8k16.row.col.f32.bf16.bf16.f32 "
        "{%0,%1,%2,%3}, {%4,%5,%6,%7}, {%8,%9}, {%0,%1,%2,%3};"
        : "+f"(c.x), "+f"(c.y), "+f"(c.z), "+f"(c.w)
        : "r"(a0), "r"(a1), "r"(a2), "r"(a3), "r"(b0), "r"(b1));
}
__device__ __forceinline__ void cpa16(float* dst, const float* src) {
    unsigned sa = (unsigned)__cvta_generic_to_shared(dst);
    asm volatile("cp.async.cg.shared.global [%0], [%1], 16;" :: "r"(sa), "l"(src));
}
#define CP_COMMIT() asm volatile("cp.async.commit_group;")
#define CP_WAIT(n)  asm volatile("cp.async.wait_group %0;" :: "n"(n))

// ---------------------------------------------------------------------------
// Kernel 0: pack Er into zero-padded bf16x2 rows [d2][EROFF + l].
// ---------------------------------------------------------------------------
__global__ void __launch_bounds__(256) erb_kernel(const float* __restrict__ Er)
{
    int idx = blockIdx.x * 256 + threadIdx.x;   // 65536 = 32 d2 x 2048 l
    int d2 = idx >> 11, l = idx & 2047;
    float2 e = *(const float2*)&Er[(size_t)l * HD + 2 * d2];
    g_erb[d2 * ERBW + EROFF + l] = pk2(e.y, e.x);
}

// ---------------------------------------------------------------------------
// Kernel 1: QKV projection — all tf32 single-pass m16n8k8, occupancy 2.
//   z=0: Q fp32 [bh][s][d].  z=1: K packed bf16x2 [bh][d2][s].
//   z=2: V tf32-bits [bh][s][d].
// ---------------------------------------------------------------------------
#define QKV_SMEM_BYTES (18432 * 4)

__global__ void __launch_bounds__(256, 2) qkv_kernel(
    const float* __restrict__ x, const float* __restrict__ Wq,
    const float* __restrict__ Wk, const float* __restrict__ Wv)
{
    extern __shared__ float sm[];
    const int z = blockIdx.z;
    const float* W = z == 0 ? Wq : (z == 1 ? Wk : Wv);
    const int m0 = blockIdx.y * 128, n0 = blockIdx.x * 128;
    const int tid = threadIdx.x, lane = tid & 31, warp = tid >> 5;
    const int g = lane >> 2, t = lane & 3;
    const int mw = (warp >> 2) * 64, nw = (warp & 3) * 32;

    float* Xs[2] = { sm, sm + 4608 };
    float* Ws[2] = { sm + 9216, sm + 13824 };
    const int r_ = tid >> 1, c_ = (tid & 1) * 16;
    #define STAGE(buf, k0) do { \
        cpa16(Xs[buf] + r_ * 36 + c_,      &x[(size_t)(m0 + r_) * EE + (k0) + c_]); \
        cpa16(Xs[buf] + r_ * 36 + c_ + 4,  &x[(size_t)(m0 + r_) * EE + (k0) + c_ + 4]); \
        cpa16(Xs[buf] + r_ * 36 + c_ + 8,  &x[(size_t)(m0 + r_) * EE + (k0) + c_ + 8]); \
        cpa16(Xs[buf] + r_ * 36 + c_ + 12, &x[(size_t)(m0 + r_) * EE + (k0) + c_ + 12]); \
        cpa16(Ws[buf] + r_ * 36 + c_,      &W[(size_t)(n0 + r_) * EE + (k0) + c_]); \
        cpa16(Ws[buf] + r_ * 36 + c_ + 4,  &W[(size_t)(n0 + r_) * EE + (k0) + c_ + 4]); \
        cpa16(Ws[buf] + r_ * 36 + c_ + 8,  &W[(size_t)(n0 + r_) * EE + (k0) + c_ + 8]); \
        cpa16(Ws[buf] + r_ * 36 + c_ + 12, &W[(size_t)(n0 + r_) * EE + (k0) + c_ + 12]); \
        CP_COMMIT(); \
    } while (0)

    float4 acc[4][4];
    #pragma unroll
    for (int m = 0; m < 4; m++)
        #pragma unroll
        for (int n = 0; n < 4; n++) acc[m][n] = make_float4(0.f, 0.f, 0.f, 0.f);

    STAGE(0, 0);
    for (int p = 0; p < 16; p++) {
        if (p < 15) STAGE((p + 1) & 1, (p + 1) * 32);
        if (p < 15) { CP_WAIT(1); } else { CP_WAIT(0); }
        __syncthreads();
        const float* Xb = Xs[p & 1];
        const float* Wb = Ws[p & 1];
        #pragma unroll
        for (int s = 0; s < 4; s++) {
            unsigned a[4][4], b[4][2];
            #pragma unroll
            for (int m = 0; m < 4; m++) {
                const float* r0 = &Xb[(mw + 16 * m + g) * 36 + 8 * s];
                const float* r1 = &Xb[(mw + 16 * m + g + 8) * 36 + 8 * s];
                a[m][0] = f2tf(r0[t]); a[m][1] = f2tf(r1[t]);
                a[m][2] = f2tf(r0[t + 4]); a[m][3] = f2tf(r1[t + 4]);
            }
            #pragma unroll
            for (int n = 0; n < 4; n++) {
                const float* w0 = &Wb[(nw + 8 * n + g) * 36 + 8 * s];
                b[n][0] = f2tf(w0[t]); b[n][1] = f2tf(w0[t + 4]);
            }
            #pragma unroll
            for (int m = 0; m < 4; m++)
                #pragma unroll
                for (int n = 0; n < 4; n++)
                    mma8(acc[m][n], a[m][0], a[m][1], a[m][2], a[m][3], b[n][0], b[n][1]);
        }
        __syncthreads();
    }

    #pragma unroll
    for (int m = 0; m < 4; m++) {
        int r0 = m0 + mw + 16 * m + g, r1 = r0 + 8;
        int b0_ = r0 >> 11, s0_ = r0 & 2047;
        int b1_ = r1 >> 11, s1_ = r1 & 2047;
        #pragma unroll
        for (int n = 0; n < 4; n++) {
            int col = n0 + nw + 8 * n + 2 * t;
            int h = col >> 6, d = col & 63;
            if (z == 0) {
                *(float2*)&g_q[(((size_t)b0_ * HH + h) * SS + s0_) * HD + d] = make_float2(acc[m][n].x, acc[m][n].y);
                *(float2*)&g_q[(((size_t)b1_ * HH + h) * SS + s1_) * HD + d] = make_float2(acc[m][n].z, acc[m][n].w);
            } else if (z == 1) {
                int d2 = d >> 1;
                g_kb[((size_t)(b0_ * HH + h) * 32 + d2) * SS + s0_] = pk2(acc[m][n].y, acc[m][n].x);
                g_kb[((size_t)(b1_ * HH + h) * 32 + d2) * SS + s1_] = pk2(acc[m][n].w, acc[m][n].z);
            } else {
                *(float2*)&g_vt[(((size_t)b0_ * HH + h) * SS + s0_) * HD + d] =
                    make_float2(__uint_as_float(f2tf(acc[m][n].x)), __uint_as_float(f2tf(acc[m][n].y)));
                *(float2*)&g_vt[(((size_t)b1_ * HH + h) * SS + s1_) * HD + d] =
                    make_float2(__uint_as_float(f2tf(acc[m][n].z)), __uint_as_float(f2tf(acc[m][n].w)));
            }
        }
    }
}

// ---------------------------------------------------------------------------
// Kernel 2: flash attention with relative-position skew — 64-row CTAs,
// 128 threads, 2 CTAs/SM. Staging is pure copy (operands pre-packed).
//
// Srel[i,j] = q_i . Er[S-1-(i-j)]  (j<=i) | 0 (j=i+1) | q_{i+1} . Er[j-i-2] (j>=i+2)
//
// S, R1, R2: bf16 m16n8k16 single-pass.  PV: tf32 m16n8k8 single-pass.
// ---------------------------------------------------------------------------
#define QP 68
#define KP2 72
#define VP 72
#define WP2 136
#define RP 84
#define SM_Q  0
#define SM_K  4420
#define SM_V  6724
#define SM_W1 11332
#define SM_W2 15684
#define SM_R  20036
#define SM_TOT_FLOATS 25412
#define SMEM_BYTES (SM_TOT_FLOATS * 4)   /* 101648 B -> 2 CTAs/SM */

__global__ void __launch_bounds__(128, 2) attn_kernel(float* __restrict__ out)
{
    extern __shared__ float sm[];
    float* Qs   = sm + SM_Q;
    unsigned* Khs = (unsigned*)(sm + SM_K);
    float* Vs   = sm + SM_V;
    unsigned* W1h = (unsigned*)(sm + SM_W1);
    unsigned* W2h = (unsigned*)(sm + SM_W2);
    float* Rscr = sm + SM_R;
    unsigned* Pb = (unsigned*)sm;
    const unsigned* Vsu = (const unsigned*)Vs;

    const int tid  = threadIdx.x;
    const int lane = tid & 31;
    const int warp = tid >> 5;
    const int g = lane >> 2;
    const int t = lane & 3;
    const int rbase = warp * 16;

    const int bh = blockIdx.y;
    const int i0 = blockIdx.x * 64;

    const float* qb0 = g_q + (size_t)bh * SS * HD;
    const unsigned* kbb = g_kb + (size_t)bh * 32 * SS;
    const float* vb0 = g_vt + (size_t)bh * SS * HD;

    for (int idx = tid; idx < 65 * 16; idx += 128) {
        int r = idx >> 4, dq = (idx & 15) * 4;
        float4 v = make_float4(0.f, 0.f, 0.f, 0.f);
        int gi = i0 + r;
        if (gi < SS) v = *(const float4*)&qb0[(size_t)gi * HD + dq];
        *(float4*)&Qs[r * QP + dq] = v;
    }
    __syncthreads();

    unsigned aq[4][4], aq2[4][4];
    {
        const float* r0 = &Qs[(rbase + g) * QP];
        const float* r1 = &Qs[(rbase + g + 8) * QP];
        const float* s0 = &Qs[(rbase + g + 1) * QP];
        const float* s1 = &Qs[(rbase + g + 9) * QP];
        #pragma unroll
        for (int s = 0; s < 4; s++) {
            float2 f0 = *(const float2*)&r0[16 * s + 2 * t];
            float2 f1 = *(const float2*)&r1[16 * s + 2 * t];
            float2 f2 = *(const float2*)&r0[16 * s + 2 * t + 8];
            float2 f3 = *(const float2*)&r1[16 * s + 2 * t + 8];
            aq[s][0] = pk2(f0.y, f0.x);
            aq[s][1] = pk2(f1.y, f1.x);
            aq[s][2] = pk2(f2.y, f2.x);
            aq[s][3] = pk2(f3.y, f3.x);
            float2 h0 = *(const float2*)&s0[16 * s + 2 * t];
            float2 h1 = *(const float2*)&s1[16 * s + 2 * t];
            float2 h2 = *(const float2*)&s0[16 * s + 2 * t + 8];
            float2 h3 = *(const float2*)&s1[16 * s + 2 * t + 8];
            aq2[s][0] = pk2(h0.y, h0.x);
            aq2[s][1] = pk2(h1.y, h1.x);
            aq2[s][2] = pk2(h2.y, h2.x);
            aq2[s][3] = pk2(h3.y, h3.x);
        }
    }
    __syncthreads();  // frag build done before Pb overwrites Qs

    float4 Oacc[8];
    #pragma unroll
    for (int n = 0; n < 8; n++) Oacc[n] = make_float4(0.f, 0.f, 0.f, 0.f);
    float m0r = -1e30f, m1r = -1e30f, l0r = 0.f, l1r = 0.f;

    const float* rp0 = &Rscr[(rbase + g) * RP];
    const float* rp1 = &Rscr[(rbase + g + 8) * RP];
    float* wr0 = &Rscr[(rbase + g) * RP + 2 * t];
    float* wr1 = &Rscr[(rbase + g + 8) * RP + 2 * t];
    unsigned* Pb0 = Pb + (rbase + g) * QP;
    unsigned* Pb1 = Pb + (rbase + g + 8) * QP;
    const int off1w = 48 - rbase;
    const int tlb = 2 * t + 15 - g;
    const int diffb = (2 * t) - (i0 + rbase + g);

    for (int j0 = 0; j0 < SS; j0 += 64) {
        __syncthreads();

        const bool need1 = (j0 <= i0 + 63);
        const bool need2 = (j0 + 63 >= i0 + 2);
        const int L1 = SS - 64 - i0 + j0;
        const int L2 = j0 - i0 - 65;

        // ---- staging: pure copies (operands pre-packed) ----
        #pragma unroll
        for (int ii = 0; ii < 16; ii++) {
            int idx = tid + ii * 128;
            int d2 = idx >> 6, j = idx & 63;
            Khs[d2 * KP2 + j] = kbb[(size_t)d2 * SS + j0 + j];
        }
        #pragma unroll
        for (int ii = 0; ii < 8; ii++) {
            int idx = tid + ii * 128;
            int j = idx >> 4, dq = (idx & 15) * 4;
            *(float4*)&Vs[j * VP + dq] = *(const float4*)&vb0[(size_t)(j0 + j) * HD + dq];
        }
        if (need1) {
            #pragma unroll
            for (int ii = 0; ii < 32; ii++) {
                int idx = tid + ii * 128;
                int d2 = idx >> 7, tl = idx & 127;
                W1h[d2 * WP2 + tl] = g_erb[d2 * ERBW + EROFF + L1 + tl];
            }
        }
        if (need2) {
            #pragma unroll
            for (int ii = 0; ii < 32; ii++) {
                int idx = tid + ii * 128;
                int d2 = idx >> 7, tl = idx & 127;
                W2h[d2 * WP2 + tl] = g_erb[d2 * ERBW + EROFF + L2 + tl];
            }
        }
        __syncthreads();

        // ---- S = Q K^T (bf16, 32 mma) ----
        float4 sacc[8];
        #pragma unroll
        for (int n = 0; n < 8; n++) {
            float4 c = make_float4(0.f, 0.f, 0.f, 0.f);
            #pragma unroll
            for (int s = 0; s < 4; s++) {
                unsigned b0 = Khs[(8 * s + t) * KP2 + 8 * n + g];
                unsigned b1 = Khs[(8 * s + t + 4) * KP2 + 8 * n + g];
                mma16(c, aq[s][0], aq[s][1], aq[s][2], aq[s][3], b0, b1);
            }
            sacc[n] = c;
        }

        const bool wneed1 = (j0 <= i0 + rbase + 15);
        const bool wneed2 = (j0 + 63 >= i0 + rbase + 2);

        if (wneed1) {
            #pragma unroll
            for (int n = 0; n < 10; n++) {
                float4 c = make_float4(0.f, 0.f, 0.f, 0.f);
                #pragma unroll
                for (int s = 0; s < 4; s++) {
                    unsigned b0 = W1h[(8 * s + t) * WP2 + off1w + 8 * n + g];
                    unsigned b1 = W1h[(8 * s + t + 4) * WP2 + off1w + 8 * n + g];
                    mma16(c, aq[s][0], aq[s][1], aq[s][2], aq[s][3], b0, b1);
                }
                wr0[8 * n] = c.x; wr0[8 * n + 1] = c.y;
                wr1[8 * n] = c.z; wr1[8 * n + 1] = c.w;
            }
            __syncwarp();
            #pragma unroll
            for (int n = 0; n < 8; n++) {
                int d00 = diffb + j0 + 8 * n;
                int tl = tlb + 8 * n;
                if (d00 <= 0)     sacc[n].x += rp0[tl];
                if (d00 + 1 <= 0) sacc[n].y += rp0[tl + 1];
                if (d00 - 8 <= 0) sacc[n].z += rp1[tl - 8];
                if (d00 - 7 <= 0) sacc[n].w += rp1[tl - 7];
            }
            __syncwarp();
        }
        if (wneed2) {
            #pragma unroll
            for (int n = 0; n < 10; n++) {
                float4 c = make_float4(0.f, 0.f, 0.f, 0.f);
                #pragma unroll
                for (int s = 0; s < 4; s++) {
                    unsigned b0 = W2h[(8 * s + t) * WP2 + off1w + 8 * n + g];
                    unsigned b1 = W2h[(8 * s + t + 4) * WP2 + off1w + 8 * n + g];
                    mma16(c, aq2[s][0], aq2[s][1], aq2[s][2], aq2[s][3], b0, b1);
                }
                wr0[8 * n] = c.x; wr0[8 * n + 1] = c.y;
                wr1[8 * n] = c.z; wr1[8 * n + 1] = c.w;
            }
            __syncwarp();
            #pragma unroll
            for (int n = 0; n < 8; n++) {
                int d00 = diffb + j0 + 8 * n;
                int tl = tlb + 8 * n;
                if (d00 >= 2)     sacc[n].x += rp0[tl];
                if (d00 + 1 >= 2) sacc[n].y += rp0[tl + 1];
                if (d00 - 8 >= 2) sacc[n].z += rp1[tl - 8];
                if (d00 - 7 >= 2) sacc[n].w += rp1[tl - 7];
            }
            __syncwarp();
        }

        // ---- scale + online softmax ----
        float mx0 = -1e30f, mx1 = -1e30f;
        #pragma unroll
        for (int n = 0; n < 8; n++) {
            sacc[n].x *= SCALE; sacc[n].y *= SCALE;
            sacc[n].z *= SCALE; sacc[n].w *= SCALE;
            mx0 = fmaxf(mx0, fmaxf(sacc[n].x, sacc[n].y));
            mx1 = fmaxf(mx1, fmaxf(sacc[n].z, sacc[n].w));
        }
        #pragma unroll
        for (int off = 1; off <= 2; off <<= 1) {
            mx0 = fmaxf(mx0, __shfl_xor_sync(0xffffffffu, mx0, off));
            mx1 = fmaxf(mx1, __shfl_xor_sync(0xffffffffu, mx1, off));
        }
        float mn0 = fmaxf(m0r, mx0), mn1 = fmaxf(m1r, mx1);
        float c0 = __expf(m0r - mn0), c1 = __expf(m1r - mn1);
        float rs0 = 0.f, rs1 = 0.f;
        #pragma unroll
        for (int n = 0; n < 8; n++) {
            sacc[n].x = __expf(sacc[n].x - mn0);
            sacc[n].y = __expf(sacc[n].y - mn0);
            sacc[n].z = __expf(sacc[n].z - mn1);
            sacc[n].w = __expf(sacc[n].w - mn1);
            rs0 += sacc[n].x + sacc[n].y;
            rs1 += sacc[n].z + sacc[n].w;
        }
        #pragma unroll
        for (int off = 1; off <= 2; off <<= 1) {
            rs0 += __shfl_xor_sync(0xffffffffu, rs0, off);
            rs1 += __shfl_xor_sync(0xffffffffu, rs1, off);
        }
        l0r = l0r * c0 + rs0;  m0r = mn0;
        l1r = l1r * c1 + rs1;  m1r = mn1;
        #pragma unroll
        for (int n = 0; n < 8; n++) {
            Oacc[n].x *= c0; Oacc[n].y *= c0;
            Oacc[n].z *= c1; Oacc[n].w *= c1;
        }

        // ---- stage P (tf32 bits, warp-private rows) ----
        #pragma unroll
        for (int n = 0; n < 8; n++) {
            Pb0[8 * n + 2 * t]     = f2tf(sacc[n].x);
            Pb0[8 * n + 2 * t + 1] = f2tf(sacc[n].y);
            Pb1[8 * n + 2 * t]     = f2tf(sacc[n].z);
            Pb1[8 * n + 2 * t + 1] = f2tf(sacc[n].w);
        }
        __syncwarp();

        // ---- O += P V  (tf32 single-pass, 64 mma) ----
        #pragma unroll
        for (int sp = 0; sp < 8; sp++) {
            unsigned a0 = Pb0[8 * sp + t];
            unsigned a1 = Pb1[8 * sp + t];
            unsigned a2 = Pb0[8 * sp + t + 4];
            unsigned a3 = Pb1[8 * sp + t + 4];
            #pragma unroll
            for (int n = 0; n < 8; n++) {
                unsigned b0 = Vsu[(8 * sp + t) * VP + 8 * n + g];
                unsigned b1 = Vsu[(8 * sp + t + 4) * VP + 8 * n + g];
                mma8(Oacc[n], a0, a1, a2, a3, b0, b1);
            }
        }
        __syncwarp();
    }

    // ---- normalize + write out [b][s][h*64+d] ----
    const int b_ = bh >> 3, h = bh & 7;
    const float inv0 = 1.0f / l0r, inv1 = 1.0f / l1r;
    float* op0 = out + ((size_t)b_ * SS + (i0 + rbase + g)) * EE + h * HD;
    float* op1 = out + ((size_t)b_ * SS + (i0 + rbase + g + 8)) * EE + h * HD;
    #pragma unroll
    for (int n = 0; n < 8; n++) {
        *(float2*)&op0[8 * n + 2 * t] = make_float2(Oacc[n].x * inv0, Oacc[n].y * inv0);
        *(float2*)&op1[8 * n + 2 * t] = make_float2(Oacc[n].z * inv1, Oacc[n].w * inv1);
    }
}

// ---------------------------------------------------------------------------
// Kernel 3: in-place LayerNorm, 2 rows/CTA, float4 per thread.
// threads 0-127 -> row 2*blk, threads 128-255 -> row 2*blk+1.
// ---------------------------------------------------------------------------
__global__ void __launch_bounds__(256) ln_kernel(
    float* __restrict__ out,
    const float* __restrict__ gamma,
    const float* __restrict__ beta)
{
    __shared__ float reds[2][4], redq[2][4];
    const int tid = threadIdx.x;
    const int rsel = tid >> 7;                 // 0 or 1
    const int tsub = tid & 127;                // thread within row
    const int row = blockIdx.x * 2 + rsel;
    float* p = out + (size_t)row * EE + tsub * 4;

    float4 v = *(const float4*)p;
    float s = v.x + v.y + v.z + v.w;
    float q = v.x * v.x + v.y * v.y + v.z * v.z + v.w * v.w;
    #pragma unroll
    for (int off = 16; off > 0; off >>= 1) {
        s += __shfl_xor_sync(0xffffffffu, s, off);
        q += __shfl_xor_sync(0xffffffffu, q, off);
    }
    const int wsub = (tid >> 5) & 3;           // warp within row
    if ((tid & 31) == 0) { reds[rsel][wsub] = s; redq[rsel][wsub] = q; }
    __syncthreads();
    s = reds[rsel][0] + reds[rsel][1] + reds[rsel][2] + reds[rsel][3];
    q = redq[rsel][0] + redq[rsel][1] + redq[rsel][2] + redq[rsel][3];

    float mu = s * (1.0f / EE);
    float var = q * (1.0f / EE) - mu * mu;
    float inv = rsqrtf(var + 1e-5f);
    float4 gm = *(const float4*)&gamma[tsub * 4];
    float4 bt = *(const float4*)&beta[tsub * 4];
    float4 r;
    r.x = (v.x - mu) * inv * gm.x + bt.x;
    r.y = (v.y - mu) * inv * gm.y + bt.y;
    r.z = (v.z - mu) * inv * gm.z + bt.z;
    r.w = (v.w - mu) * inv * gm.w + bt.w;
    *(float4*)p = r;
}

// ---------------------------------------------------------------------------
extern "C" void kernel_launch(void* const* d_in, const int* in_sizes, int n_in,
                              void* d_out, int out_size)
{
    const float* x     = (const float*)d_in[0];
    const float* Wq    = (const float*)d_in[1];
    const float* Wk    = (const float*)d_in[2];
    const float* Wv    = (const float*)d_in[3];
    const float* Er    = (const float*)d_in[4];
    const float* gamma = (const float*)d_in[5];
    const float* beta  = (const float*)d_in[6];
    float* out = (float*)d_out;

    cudaFuncSetAttribute(qkv_kernel, cudaFuncAttributeMaxDynamicSharedMemorySize, QKV_SMEM_BYTES);
    cudaFuncSetAttribute(attn_kernel, cudaFuncAttributeMaxDynamicSharedMemorySize, SMEM_BYTES);

    erb_kernel<<<256, 256>>>(Er);
    qkv_kernel<<<dim3(EE / 128, (BB * SS) / 128, 3), 256, QKV_SMEM_BYTES>>>(x, Wq, Wk, Wv);
    attn_kernel<<<dim3(SS / 64, BB * HH), 128, SMEM_BYTES>>>(out);
    ln_kernel<<<BB * SS / 2, 256>>>(out, gamma, beta);
}